// round 3
// baseline (speedup 1.0000x reference)
#include <cuda_runtime.h>

typedef unsigned long long ull;

#define BB 4
#define CC 2048
#define HW 32
#define HID 512
#define AA 9
#define GG 20
#define NN (32*32*9)        /* 9216 anchors per image */
#define MM (4*32*32)        /* 4096 pixels            */
#define KK (2048*9)         /* 18432 reduction dim    */
#define EPSF 1e-8f

/* ---------------- scratch (static device globals; no allocation) ------- */
__device__ float g_wt[KK * HID];     /* conv1 weights transposed [k][oc]  */
__device__ float g_hid[MM * HID];    /* relu(conv1) pixel-major [m][oc]   */
__device__ float g_po[MM * 45];      /* head outputs per pixel: 9 conf + 36 reg */
__device__ float g_maxpg[BB * GG];   /* max IoU per (b,g)                 */
__device__ float g_clsp[144];
__device__ float g_regp[144];

/* ---------------- small helpers ---------------------------------------- */
__device__ __forceinline__ ull pack2(float lo, float hi) {
    ull r; asm("mov.b64 %0, {%1,%2};" : "=l"(r) : "f"(lo), "f"(hi)); return r;
}
__device__ __forceinline__ float2 unpack2(ull v) {
    float2 f; asm("mov.b64 {%0,%1}, %2;" : "=f"(f.x), "=f"(f.y) : "l"(v)); return f;
}
#define FMA2(d, a, b) asm("fma.rn.f32x2 %0, %1, %2, %3;" : "=l"(d) : "l"(a), "l"(b), "l"(d))

__device__ __forceinline__ float softplusf(float z) {
    return fmaxf(z, 0.f) + log1pf(expf(-fabsf(z)));
}

/* anchor for flat index n within one image; intrinsics for bitwise repeatability */
__device__ __forceinline__ void anchor_of(int n, float& x1, float& y1, float& x2,
                                          float& y2, float& areaA) {
    int cell = n / 9;  int a = n - cell * 9;
    int yI = cell >> 5, xI = cell & 31;
    int s = a / 3;     int r = a - s * 3;
    float aw = (float)(2 * (s + 1));                 /* 2,4,6  exact */
    float ah = __fmul_rn(aw, 0.5f + 0.5f * (float)r);/* exact halves */
    float xc = (float)xI + 0.5f, yc = (float)yI + 0.5f;
    float hx = __fmul_rn(0.5f, aw), hy = __fmul_rn(0.5f, ah);
    x1 = fminf(fmaxf(__fsub_rn(xc, hx), 0.f), 32.f);
    y1 = fminf(fmaxf(__fsub_rn(yc, hy), 0.f), 32.f);
    x2 = fminf(fmaxf(__fadd_rn(xc, hx), 0.f), 32.f);
    y2 = fminf(fmaxf(__fadd_rn(yc, hy), 0.f), 32.f);
    areaA = __fmul_rn(__fsub_rn(x2, x1), __fsub_rn(y2, y1));
}

__device__ __forceinline__ float iou_f(float ax1, float ay1, float ax2, float ay2,
                                       float areaA, float gx1, float gy1, float gx2,
                                       float gy2, float areaG) {
    float lx = fmaxf(ax1, gx1), ly = fmaxf(ay1, gy1);
    float rx = fminf(ax2, gx2), ry = fminf(ay2, gy2);
    float iw = fmaxf(__fsub_rn(rx, lx), 0.f);
    float ih = fmaxf(__fsub_rn(ry, ly), 0.f);
    float inter = __fmul_rn(iw, ih);
    float den = __fadd_rn(__fsub_rn(__fadd_rn(areaA, areaG), inter), EPSF);
    return __fdiv_rn(inter, den);
}

/* ---------------- kernel 1: transpose conv1 weights [OC][K] -> [K][OC] -- */
__global__ void k_transpose(const float* __restrict__ w) {
    __shared__ float t[32][33];
    int kb = blockIdx.x * 32, ob = blockIdx.y * 32;
    int tx = threadIdx.x, ty = threadIdx.y;
#pragma unroll
    for (int i = ty; i < 32; i += 8)
        t[i][tx] = w[(size_t)(ob + i) * KK + kb + tx];
    __syncthreads();
#pragma unroll
    for (int i = ty; i < 32; i += 8)
        g_wt[(size_t)(kb + i) * HID + ob + tx] = t[tx][i];
}

/* ---------------- kernel 2: conv1 (implicit GEMM, f32x2 FFMA) ----------- */
/* M=4096 pixels, N=512 oc, K=18432. Tile 128x128, BK=36 (4 channels x 9). */
__global__ __launch_bounds__(256, 1) void k_conv1(const float* __restrict__ x,
                                                  const float* __restrict__ bias1) {
    __shared__ float As[36 * 128];
    __shared__ float Bs[36 * 128];
    int tid = threadIdx.x;
    int m0 = blockIdx.x * 128, n0 = blockIdx.y * 128;
    int tx = tid & 15, ty = tid >> 4;
    int tH = tid >> 7, mm = tid & 127;

    /* per-thread im2col gather offsets (fixed kk set = 2i + tH) */
    int m = m0 + mm;
    int bb = m >> 10, y0 = (m >> 5) & 31, x0 = m & 31;
    int offA[18];
#pragma unroll
    for (int i = 0; i < 18; i++) {
        int kk = 2 * i + tH;
        int dc = kk / 9;  int t = kk - dc * 9;
        int dy = t / 3 - 1;
        int dx = t - (t / 3) * 3 - 1;
        int yy = y0 + dy, xx = x0 + dx;
        bool v = ((unsigned)yy < 32u) && ((unsigned)xx < 32u);
        offA[i] = v ? (((bb * 2048 + dc) << 10) + (yy << 5) + xx) : -1;
    }
    const float* wB = g_wt + (size_t)tH * 512 + n0 + mm;
    float* sA = As + tH * 128 + mm;
    float* sB = Bs + tH * 128 + mm;

    ull acc[8][4];
#pragma unroll
    for (int i = 0; i < 8; i++)
#pragma unroll
        for (int j = 0; j < 4; j++) acc[i][j] = 0ull;

    float rA[18], rB[18];
#pragma unroll
    for (int i = 0; i < 18; i++) {
        rA[i] = (offA[i] >= 0) ? x[offA[i]] : 0.f;
        rB[i] = wB[i * 1024];
    }

    for (int it = 0; it < 512; it++) {
#pragma unroll
        for (int i = 0; i < 18; i++) { sA[i * 256] = rA[i]; sB[i * 256] = rB[i]; }
        __syncthreads();
        if (it + 1 < 512) {
            int cb = (it + 1) * 4096;              /* +4 channels of 1024 px */
            int kb = (it + 1) * 18432;             /* +36 wt rows of 512     */
#pragma unroll
            for (int i = 0; i < 18; i++) {
                rA[i] = (offA[i] >= 0) ? x[offA[i] + cb] : 0.f;
                rB[i] = wB[i * 1024 + kb];
            }
        }
#pragma unroll 9
        for (int kk = 0; kk < 36; kk++) {
            float4 a0 = *(const float4*)(As + kk * 128 + ty * 8);
            float4 a1 = *(const float4*)(As + kk * 128 + ty * 8 + 4);
            float4 b0 = *(const float4*)(Bs + kk * 128 + tx * 8);
            float4 b1 = *(const float4*)(Bs + kk * 128 + tx * 8 + 4);
            ull bp[4], ap[8];
            bp[0] = pack2(b0.x, b0.y); bp[1] = pack2(b0.z, b0.w);
            bp[2] = pack2(b1.x, b1.y); bp[3] = pack2(b1.z, b1.w);
            ap[0] = pack2(a0.x, a0.x); ap[1] = pack2(a0.y, a0.y);
            ap[2] = pack2(a0.z, a0.z); ap[3] = pack2(a0.w, a0.w);
            ap[4] = pack2(a1.x, a1.x); ap[5] = pack2(a1.y, a1.y);
            ap[6] = pack2(a1.z, a1.z); ap[7] = pack2(a1.w, a1.w);
#pragma unroll
            for (int i = 0; i < 8; i++)
#pragma unroll
                for (int j = 0; j < 4; j++) FMA2(acc[i][j], ap[i], bp[j]);
        }
        __syncthreads();
    }

    /* epilogue: bias + relu, pixel-major store */
    float bv[8];
#pragma unroll
    for (int j = 0; j < 8; j++) bv[j] = bias1[n0 + tx * 8 + j];
#pragma unroll
    for (int i = 0; i < 8; i++) {
        float o[8];
#pragma unroll
        for (int j = 0; j < 4; j++) {
            float2 p = unpack2(acc[i][j]);
            o[2 * j]     = fmaxf(p.x + bv[2 * j], 0.f);
            o[2 * j + 1] = fmaxf(p.y + bv[2 * j + 1], 0.f);
        }
        float4* dst = (float4*)(g_hid + (size_t)(m0 + ty * 8 + i) * 512 + n0 + tx * 8);
        dst[0] = make_float4(o[0], o[1], o[2], o[3]);
        dst[1] = make_float4(o[4], o[5], o[6], o[7]);
    }
}

/* ---------------- kernel 3: 1x1 heads (conf 9 + reg 36 = 45 outs) ------- */
__global__ __launch_bounds__(256) void k_heads(const float* __restrict__ cw,
                                               const float* __restrict__ cb,
                                               const float* __restrict__ rw,
                                               const float* __restrict__ rb) {
    __shared__ float As[128][33];
    __shared__ float Bs[32][48];
    int tid = threadIdx.x;
    int m0 = blockIdx.x * 128;
    int tx = tid & 15, ty = tid >> 4;
    float acc[8][3] = {};
    for (int k0 = 0; k0 < 512; k0 += 32) {
#pragma unroll
        for (int i = 0; i < 16; i++) {
            int idx = i * 256 + tid;
            int mmi = idx >> 5, kki = idx & 31;
            As[mmi][kki] = g_hid[(size_t)(m0 + mmi) * 512 + k0 + kki];
        }
#pragma unroll
        for (int i = 0; i < 6; i++) {
            int idx = i * 256 + tid;
            int kki = idx / 48, nn = idx - kki * 48;
            float v = 0.f;
            if (nn < 9)       v = cw[nn * 512 + k0 + kki];
            else if (nn < 45) v = rw[(nn - 9) * 512 + k0 + kki];
            Bs[kki][nn] = v;
        }
        __syncthreads();
#pragma unroll
        for (int kki = 0; kki < 32; kki++) {
            float a[8], b3[3];
#pragma unroll
            for (int i = 0; i < 8; i++) a[i] = As[ty * 8 + i][kki];
#pragma unroll
            for (int j = 0; j < 3; j++) b3[j] = Bs[kki][tx * 3 + j];
#pragma unroll
            for (int i = 0; i < 8; i++)
#pragma unroll
                for (int j = 0; j < 3; j++) acc[i][j] += a[i] * b3[j];
        }
        __syncthreads();
    }
#pragma unroll
    for (int i = 0; i < 8; i++)
#pragma unroll
        for (int j = 0; j < 3; j++) {
            int n = tx * 3 + j;
            if (n < 45) {
                float bias = (n < 9) ? cb[n] : rb[n - 9];
                g_po[(size_t)(m0 + ty * 8 + i) * 45 + n] = acc[i][j] + bias;
            }
        }
}

/* ---------------- kernel 4: max IoU per (b,g) --------------------------- */
__global__ void k_maxpg(const float* __restrict__ gtb) {
    int b = blockIdx.x / GG, g = blockIdx.x % GG;
    int tid = threadIdx.x;
    float gx1 = __fmul_rn(gtb[(b * GG + g) * 4 + 0], 0.03125f);
    float gy1 = __fmul_rn(gtb[(b * GG + g) * 4 + 1], 0.03125f);
    float gx2 = __fmul_rn(gtb[(b * GG + g) * 4 + 2], 0.03125f);
    float gy2 = __fmul_rn(gtb[(b * GG + g) * 4 + 3], 0.03125f);
    float areaG = __fmul_rn(__fsub_rn(gx2, gx1), __fsub_rn(gy2, gy1));
    float mx = 0.f;
    for (int n = tid; n < NN; n += 256) {
        float x1, y1, x2, y2, aA;
        anchor_of(n, x1, y1, x2, y2, aA);
        mx = fmaxf(mx, iou_f(x1, y1, x2, y2, aA, gx1, gy1, gx2, gy2, areaG));
    }
    __shared__ float red[256];
    red[tid] = mx;
    __syncthreads();
    for (int s = 128; s > 0; s >>= 1) {
        if (tid < s) red[tid] = fmaxf(red[tid], red[tid + s]);
        __syncthreads();
    }
    if (tid == 0) g_maxpg[blockIdx.x] = red[0];
}

/* ---------------- kernel 5: assign + losses + proposals ----------------- */
__global__ void k_loss(const float* __restrict__ gtb, float* __restrict__ out) {
    __shared__ float sg[GG][4], sArea[GG], sMpg[GG];
    __shared__ float redc[256], redr[256];
    int tid = threadIdx.x;
    int b = blockIdx.x / 36;
    int gid = blockIdx.x * 256 + tid;      /* b*9216 + n */
    int n = gid - b * NN;

    if (tid < 80) sg[tid >> 2][tid & 3] = __fmul_rn(gtb[b * 80 + tid], 0.03125f);
    __syncthreads();
    if (tid < GG) {
        sArea[tid] = __fmul_rn(__fsub_rn(sg[tid][2], sg[tid][0]),
                               __fsub_rn(sg[tid][3], sg[tid][1]));
        sMpg[tid] = g_maxpg[b * GG + tid];
    }
    __syncthreads();

    float x1, y1, x2, y2, aA;
    anchor_of(n, x1, y1, x2, y2, aA);

    float maxi = -1e30f; int gi = 0; bool pos = false;
#pragma unroll
    for (int g = 0; g < GG; g++) {
        float io = iou_f(x1, y1, x2, y2, aA, sg[g][0], sg[g][1], sg[g][2], sg[g][3],
                         sArea[g]);
        if (io > 0.7f) pos = true;
        if (io == sMpg[g] && sMpg[g] > EPSF) pos = true;
        if (io > maxi) { maxi = io; gi = g; }
    }
    bool neg = (maxi < 0.3f) && !pos;
    float posf = pos ? 1.f : 0.f;

    float gx1 = sg[gi][0], gy1 = sg[gi][1], gx2 = sg[gi][2], gy2 = sg[gi][3];

    float acx = (x1 + x2) * 0.5f, acy = (y1 + y2) * 0.5f;
    float aw = x2 - x1, ah = y2 - y1;
    float gcx = (gx1 + gx2) * 0.5f, gcy = (gy1 + gy2) * 0.5f;
    float gw = gx2 - gx1, gh = gy2 - gy1;
    float t0 = (gcx - acx) / (aw + EPSF);
    float t1 = (gcy - acy) / (ah + EPSF);
    float t2 = logf((gw + EPSF) / (aw + EPSF));
    float t3 = logf((gh + EPSF) / (ah + EPSF));

    int cell = n / 9; int a = n - cell * 9;
    size_t pb = (size_t)(b * 1024 + cell) * 45;
    float conf = g_po[pb + a];
    float o0 = g_po[pb + 9 + a * 4 + 0];
    float o1 = g_po[pb + 9 + a * 4 + 1];
    float o2 = g_po[pb + 9 + a * 4 + 2];
    float o3 = g_po[pb + 9 + a * 4 + 3];

    float clsv = pos ? softplusf(-conf) : (neg ? softplusf(conf) : 0.f);
    float regv = 0.f;
    if (pos) {
        float d0 = o0 - t0, d1 = o1 - t1, d2 = o2 - t2, d3 = o3 - t3;
        float s0 = fabsf(d0) < 1.f ? 0.5f * d0 * d0 : fabsf(d0) - 0.5f;
        float s1 = fabsf(d1) < 1.f ? 0.5f * d1 * d1 : fabsf(d1) - 0.5f;
        float s2 = fabsf(d2) < 1.f ? 0.5f * d2 * d2 : fabsf(d2) - 0.5f;
        float s3 = fabsf(d3) < 1.f ? 0.5f * d3 * d3 : fabsf(d3) - 0.5f;
        regv = s0 + s1 + s2 + s3;
    }

    /* proposals */
    float pcx = acx + o0 * aw, pcy = acy + o1 * ah;
    float pw = aw * expf(o2), ph = ah * expf(o3);
    float* pr = out + 1 + (size_t)gid * 4;
    pr[0] = (pcx - pw * 0.5f) * posf;
    pr[1] = (pcy - ph * 0.5f) * posf;
    pr[2] = (pcx + pw * 0.5f) * posf;
    pr[3] = (pcy + ph * 0.5f) * posf;
    out[1 + (size_t)BB * NN * 4 + gid] = posf;

    /* deterministic block reduction */
    redc[tid] = clsv; redr[tid] = regv;
    __syncthreads();
    for (int s = 128; s > 0; s >>= 1) {
        if (tid < s) { redc[tid] += redc[tid + s]; redr[tid] += redr[tid + s]; }
        __syncthreads();
    }
    if (tid == 0) { g_clsp[blockIdx.x] = redc[0]; g_regp[blockIdx.x] = redr[0]; }
}

/* ---------------- kernel 6: finalize scalar loss ------------------------ */
__global__ void k_fin(float* __restrict__ out) {
    float c = 0.f, r = 0.f;
    for (int i = 0; i < 144; i++) { c += g_clsp[i]; r += g_regp[i]; }
    out[0] = (c + 5.f * r) * 0.25f;
}

/* ---------------- launch ------------------------------------------------ */
extern "C" void kernel_launch(void* const* d_in, const int* in_sizes, int n_in,
                              void* d_out, int out_size) {
    const float* fm  = (const float*)d_in[0];
    const float* gtb = (const float*)d_in[1];
    /* d_in[2] = gt_classes (unused by reference loss) */
    const float* w1  = (const float*)d_in[3];
    const float* b1  = (const float*)d_in[4];
    const float* cw  = (const float*)d_in[5];
    const float* cb  = (const float*)d_in[6];
    const float* rw  = (const float*)d_in[7];
    const float* rb  = (const float*)d_in[8];
    float* out = (float*)d_out;

    k_transpose<<<dim3(KK / 32, HID / 32), dim3(32, 8)>>>(w1);
    k_conv1<<<dim3(32, 4), 256>>>(fm, b1);
    k_heads<<<32, 256>>>(cw, cb, rw, rb);
    k_maxpg<<<BB * GG, 256>>>(gtb);
    k_loss<<<144, 256>>>(gtb, out);
    k_fin<<<1, 1>>>(out);
}

// round 5
// speedup vs baseline: 1.3538x; 1.3538x over previous
#include <cuda_runtime.h>
#include <cstdint>

typedef unsigned int u32;

#define BB 4
#define HID 512
#define GG 20
#define NN (32*32*9)
#define MM (4*32*32)
#define KK (2048*9)
#define KT 32
#define KTILES (KK/KT)        /* 576 */
#define SAS 136               /* smem row stride (floats), 136%32==8 -> conflict-free */
#define ABYTES (KT*SAS*4)     /* 17408 */
#define AFLOATS (KT*SAS)      /* 4352  */
#define SMEM_BYTES (4*ABYTES) /* A x2 buf + B x2 buf = 69632 */
#define EPSF 1e-8f

/* ---------------- scratch (static device globals; no allocation) ------- */
__device__ float g_hid[MM * HID];             /* relu(conv1) pixel-major */
__device__ float g_po[MM * 45];               /* per pixel: 9 conf + 36 reg */
__device__ float g_maxpg[BB * GG];
__device__ float g_clsp[144];
__device__ float g_regp[144];

/* ---------------- helpers ---------------------------------------------- */
__device__ __forceinline__ float tf32r(float x) {
    float r; asm("cvt.rna.tf32.f32 %0, %1;" : "=f"(r) : "f"(x)); return r;
}
__device__ __forceinline__ void mma_tf32(float& d0, float& d1, float& d2, float& d3,
                                         u32 a0, u32 a1, u32 a2, u32 a3,
                                         u32 b0, u32 b1) {
    asm volatile(
        "mma.sync.aligned.m16n8k8.row.col.f32.tf32.tf32.f32 "
        "{%0,%1,%2,%3}, {%4,%5,%6,%7}, {%8,%9}, {%0,%1,%2,%3};"
        : "+f"(d0), "+f"(d1), "+f"(d2), "+f"(d3)
        : "r"(a0), "r"(a1), "r"(a2), "r"(a3), "r"(b0), "r"(b1));
}
__device__ __forceinline__ float softplusf(float z) {
    return fmaxf(z, 0.f) + log1pf(expf(-fabsf(z)));
}
__device__ __forceinline__ void anchor_of(int n, float& x1, float& y1, float& x2,
                                          float& y2, float& areaA) {
    int cell = n / 9;  int a = n - cell * 9;
    int yI = cell >> 5, xI = cell & 31;
    int s = a / 3;     int r = a - s * 3;
    float aw = (float)(2 * (s + 1));
    float ah = __fmul_rn(aw, 0.5f + 0.5f * (float)r);
    float xc = (float)xI + 0.5f, yc = (float)yI + 0.5f;
    float hx = __fmul_rn(0.5f, aw), hy = __fmul_rn(0.5f, ah);
    x1 = fminf(fmaxf(__fsub_rn(xc, hx), 0.f), 32.f);
    y1 = fminf(fmaxf(__fsub_rn(yc, hy), 0.f), 32.f);
    x2 = fminf(fmaxf(__fadd_rn(xc, hx), 0.f), 32.f);
    y2 = fminf(fmaxf(__fadd_rn(yc, hy), 0.f), 32.f);
    areaA = __fmul_rn(__fsub_rn(x2, x1), __fsub_rn(y2, y1));
}
__device__ __forceinline__ float iou_f(float ax1, float ay1, float ax2, float ay2,
                                       float areaA, float gx1, float gy1, float gx2,
                                       float gy2, float areaG) {
    float lx = fmaxf(ax1, gx1), ly = fmaxf(ay1, gy1);
    float rx = fminf(ax2, gx2), ry = fminf(ay2, gy2);
    float iw = fmaxf(__fsub_rn(rx, lx), 0.f);
    float ih = fmaxf(__fsub_rn(ry, ly), 0.f);
    float inter = __fmul_rn(iw, ih);
    float den = __fadd_rn(__fsub_rn(__fadd_rn(areaA, areaG), inter), EPSF);
    return __fdiv_rn(inter, den);
}

/* ============ kernel 1: conv1 via mma.sync tf32 ========================= */
/* GEMM M=4096 N=512 K=18432. CTA 128x128xKT32. grid (32,4). 256 thr.      */
__global__ __launch_bounds__(256, 1) void k_convmma(const float* __restrict__ fm,
                                                    const float* __restrict__ w1,
                                                    const float* __restrict__ b1) {
    extern __shared__ float sm[];              /* [A0 A1 B0 B1] stride AFLOATS */
    const int tid = threadIdx.x;
    const int lane = tid & 31, wid = tid >> 5;
    const int g = lane >> 2, tig = lane & 3;
    const int wm = wid >> 2, wn = wid & 3;     /* warp grid 2x4, tile 64x32 */
    const int m0 = blockIdx.x * 128, n0 = blockIdx.y * 128;

    const int mloc = tid & 127, kh = tid >> 7; /* producer role */

    /* per-thread im2col state for pixel m0+mloc */
    const int m = m0 + mloc;
    const int bbi = m >> 10, y0 = (m >> 5) & 31, x0 = m & 31;
    const int P = (bbi << 21) + (y0 << 5) + x0;
    int vmask = 0;
#pragma unroll
    for (int t = 0; t < 9; t++) {
        int dy = t / 3 - 1, dx = t - (t / 3) * 3 - 1;
        if ((unsigned)(y0 + dy) < 32u && (unsigned)(x0 + dx) < 32u) vmask |= 1 << t;
    }
    const float* wrow = w1 + (size_t)(n0 + mloc) * KK + kh * 16;

    float acc[4][4][4];
#pragma unroll
    for (int i = 0; i < 4; i++)
#pragma unroll
        for (int j = 0; j < 4; j++)
#pragma unroll
            for (int c = 0; c < 4; c++) acc[i][j][c] = 0.f;

    float av[16]; float4 bv[4];

    /* ---- fetch stage 'it' into registers ---- */
#define FETCH(it) do {                                                        \
        int kg = (it) * KT + kh * 16;                                         \
        int dc = kg / 9; int t9 = kg - dc * 9;                                \
        int q = t9 / 3;                                                       \
        int off = P + (dc << 10) + ((q - 1) << 5) + (t9 - q * 3 - 1);         \
        _Pragma("unroll")                                                     \
        for (int c = 0; c < 16; c++) {                                        \
            float v = 0.f;                                                    \
            if ((vmask >> t9) & 1) v = __ldg(fm + off);                       \
            av[c] = tf32r(v);                                                 \
            t9++; off++;                                                      \
            if (t9 == 3 || t9 == 6) off += 29;                                \
            else if (t9 == 9) { t9 = 0; off += 957; }                         \
        }                                                                     \
        const float4* bp = (const float4*)(wrow + (it) * KT);                 \
        _Pragma("unroll")                                                     \
        for (int q4 = 0; q4 < 4; q4++) {                                      \
            float4 x = __ldg(bp + q4);                                        \
            bv[q4] = make_float4(tf32r(x.x), tf32r(x.y), tf32r(x.z), tf32r(x.w)); \
        }                                                                     \
    } while (0)

    /* ---- store regs into smem buffer 'bf' ---- */
#define STORE(bf) do {                                                        \
        float* As = sm + (bf) * AFLOATS;                                      \
        float* Bs = sm + 2 * AFLOATS + (bf) * AFLOATS;                        \
        _Pragma("unroll")                                                     \
        for (int c = 0; c < 16; c++) {                                        \
            As[(kh * 16 + c) * SAS + mloc] = av[c];                           \
            Bs[(kh * 16 + c) * SAS + mloc] =                                  \
                ((const float*)bv)[c];                                        \
        }                                                                     \
    } while (0)

    FETCH(0);
    STORE(0);
    __syncthreads();

    for (int it = 0; it < KTILES; it++) {
        const int cur = it & 1;
        if (it + 1 < KTILES) FETCH(it + 1);

        const float* As = sm + cur * AFLOATS;
        const float* Bs = sm + 2 * AFLOATS + cur * AFLOATS;
#pragma unroll
        for (int ks = 0; ks < 4; ks++) {
            const float* Ak = As + (ks * 8 + tig) * SAS + wm * 64 + g;
            const float* Bk = Bs + (ks * 8 + tig) * SAS + wn * 32 + g;
            u32 af[4][4], bf2[4][2];
#pragma unroll
            for (int i = 0; i < 4; i++) {
                af[i][0] = __float_as_uint(Ak[i * 16]);
                af[i][1] = __float_as_uint(Ak[i * 16 + 8]);
                af[i][2] = __float_as_uint(Ak[i * 16 + 4 * SAS]);
                af[i][3] = __float_as_uint(Ak[i * 16 + 8 + 4 * SAS]);
            }
#pragma unroll
            for (int j = 0; j < 4; j++) {
                bf2[j][0] = __float_as_uint(Bk[j * 8]);
                bf2[j][1] = __float_as_uint(Bk[j * 8 + 4 * SAS]);
            }
#pragma unroll
            for (int i = 0; i < 4; i++)
#pragma unroll
                for (int j = 0; j < 4; j++)
                    mma_tf32(acc[i][j][0], acc[i][j][1], acc[i][j][2], acc[i][j][3],
                             af[i][0], af[i][1], af[i][2], af[i][3],
                             bf2[j][0], bf2[j][1]);
        }
        __syncthreads();
        if (it + 1 < KTILES) {
            STORE(cur ^ 1);
            __syncthreads();
        }
    }

    /* ---- epilogue: bias + relu -> g_hid ---- */
#pragma unroll
    for (int j = 0; j < 4; j++) {
        int nb = n0 + wn * 32 + j * 8 + 2 * tig;
        float bb0 = b1[nb], bb1 = b1[nb + 1];
#pragma unroll
        for (int i = 0; i < 4; i++) {
            int ma = m0 + wm * 64 + i * 16 + g;
            float2* d0 = (float2*)(g_hid + (size_t)ma * 512 + nb);
            float2* d1 = (float2*)(g_hid + (size_t)(ma + 8) * 512 + nb);
            *d0 = make_float2(fmaxf(acc[i][j][0] + bb0, 0.f),
                              fmaxf(acc[i][j][1] + bb1, 0.f));
            *d1 = make_float2(fmaxf(acc[i][j][2] + bb0, 0.f),
                              fmaxf(acc[i][j][3] + bb1, 0.f));
        }
    }
}

/* ============ kernel 2: 1x1 heads (conf 9 + reg 36) ===================== */
__global__ __launch_bounds__(256) void k_heads(const float* __restrict__ cw,
                                               const float* __restrict__ cb,
                                               const float* __restrict__ rw,
                                               const float* __restrict__ rb) {
    __shared__ float As[128][33];
    __shared__ float Bs[32][48];
    int tid = threadIdx.x;
    int m0 = blockIdx.x * 128;
    int tx = tid & 15, ty = tid >> 4;
    float acc[8][3] = {};
    for (int k0 = 0; k0 < 512; k0 += 32) {
#pragma unroll
        for (int i = 0; i < 16; i++) {
            int idx = i * 256 + tid;
            int mmi = idx >> 5, kki = idx & 31;
            As[mmi][kki] = g_hid[(size_t)(m0 + mmi) * 512 + k0 + kki];
        }
#pragma unroll
        for (int i = 0; i < 6; i++) {
            int idx = i * 256 + tid;
            int kki = idx / 48, nn = idx - kki * 48;
            float v = 0.f;
            if (nn < 9)       v = cw[nn * 512 + k0 + kki];
            else if (nn < 45) v = rw[(nn - 9) * 512 + k0 + kki];
            Bs[kki][nn] = v;
        }
        __syncthreads();
#pragma unroll
        for (int kki = 0; kki < 32; kki++) {
            float a[8], b3[3];
#pragma unroll
            for (int i = 0; i < 8; i++) a[i] = As[ty * 8 + i][kki];
#pragma unroll
            for (int j = 0; j < 3; j++) b3[j] = Bs[kki][tx * 3 + j];
#pragma unroll
            for (int i = 0; i < 8; i++)
#pragma unroll
                for (int j = 0; j < 3; j++) acc[i][j] += a[i] * b3[j];
        }
        __syncthreads();
    }
#pragma unroll
    for (int i = 0; i < 8; i++)
#pragma unroll
        for (int j = 0; j < 3; j++) {
            int n = tx * 3 + j;
            if (n < 45) {
                float bias = (n < 9) ? cb[n] : rb[n - 9];
                g_po[(size_t)(m0 + ty * 8 + i) * 45 + n] = acc[i][j] + bias;
            }
        }
}

/* ============ kernel 3: max IoU per (b,g) =============================== */
__global__ void k_maxpg(const float* __restrict__ gtb) {
    int b = blockIdx.x / GG, g = blockIdx.x % GG;
    int tid = threadIdx.x;
    float gx1 = __fmul_rn(gtb[(b * GG + g) * 4 + 0], 0.03125f);
    float gy1 = __fmul_rn(gtb[(b * GG + g) * 4 + 1], 0.03125f);
    float gx2 = __fmul_rn(gtb[(b * GG + g) * 4 + 2], 0.03125f);
    float gy2 = __fmul_rn(gtb[(b * GG + g) * 4 + 3], 0.03125f);
    float areaG = __fmul_rn(__fsub_rn(gx2, gx1), __fsub_rn(gy2, gy1));
    float mx = 0.f;
    for (int n = tid; n < NN; n += 256) {
        float x1, y1, x2, y2, aA;
        anchor_of(n, x1, y1, x2, y2, aA);
        mx = fmaxf(mx, iou_f(x1, y1, x2, y2, aA, gx1, gy1, gx2, gy2, areaG));
    }
    __shared__ float red[256];
    red[tid] = mx;
    __syncthreads();
    for (int s = 128; s > 0; s >>= 1) {
        if (tid < s) red[tid] = fmaxf(red[tid], red[tid + s]);
        __syncthreads();
    }
    if (tid == 0) g_maxpg[blockIdx.x] = red[0];
}

/* ============ kernel 4: assign + losses + proposals ===================== */
__global__ void k_loss(const float* __restrict__ gtb, float* __restrict__ out) {
    __shared__ float sg[GG][4], sArea[GG], sMpg[GG];
    __shared__ float redc[256], redr[256];
    int tid = threadIdx.x;
    int b = blockIdx.x / 36;
    int gid = blockIdx.x * 256 + tid;
    int n = gid - b * NN;

    if (tid < 80) sg[tid >> 2][tid & 3] = __fmul_rn(gtb[b * 80 + tid], 0.03125f);
    __syncthreads();
    if (tid < GG) {
        sArea[tid] = __fmul_rn(__fsub_rn(sg[tid][2], sg[tid][0]),
                               __fsub_rn(sg[tid][3], sg[tid][1]));
        sMpg[tid] = g_maxpg[b * GG + tid];
    }
    __syncthreads();

    float x1, y1, x2, y2, aA;
    anchor_of(n, x1, y1, x2, y2, aA);

    float maxi = -1e30f; int gi = 0; bool pos = false;
#pragma unroll
    for (int g = 0; g < GG; g++) {
        float io = iou_f(x1, y1, x2, y2, aA, sg[g][0], sg[g][1], sg[g][2], sg[g][3],
                         sArea[g]);
        if (io > 0.7f) pos = true;
        if (io == sMpg[g] && sMpg[g] > EPSF) pos = true;
        if (io > maxi) { maxi = io; gi = g; }
    }
    bool neg = (maxi < 0.3f) && !pos;
    float posf = pos ? 1.f : 0.f;

    float gx1 = sg[gi][0], gy1 = sg[gi][1], gx2 = sg[gi][2], gy2 = sg[gi][3];

    float acx = (x1 + x2) * 0.5f, acy = (y1 + y2) * 0.5f;
    float aw = x2 - x1, ah = y2 - y1;
    float gcx = (gx1 + gx2) * 0.5f, gcy = (gy1 + gy2) * 0.5f;
    float gw = gx2 - gx1, gh = gy2 - gy1;
    float t0 = (gcx - acx) / (aw + EPSF);
    float t1 = (gcy - acy) / (ah + EPSF);
    float t2 = logf((gw + EPSF) / (aw + EPSF));
    float t3 = logf((gh + EPSF) / (ah + EPSF));

    int cell = n / 9; int a = n - cell * 9;
    size_t pb = (size_t)(b * 1024 + cell) * 45;
    float conf = g_po[pb + a];
    float o0 = g_po[pb + 9 + a * 4 + 0];
    float o1 = g_po[pb + 9 + a * 4 + 1];
    float o2 = g_po[pb + 9 + a * 4 + 2];
    float o3 = g_po[pb + 9 + a * 4 + 3];

    float clsv = pos ? softplusf(-conf) : (neg ? softplusf(conf) : 0.f);
    float regv = 0.f;
    if (pos) {
        float d0 = o0 - t0, d1 = o1 - t1, d2 = o2 - t2, d3 = o3 - t3;
        float s0 = fabsf(d0) < 1.f ? 0.5f * d0 * d0 : fabsf(d0) - 0.5f;
        float s1 = fabsf(d1) < 1.f ? 0.5f * d1 * d1 : fabsf(d1) - 0.5f;
        float s2 = fabsf(d2) < 1.f ? 0.5f * d2 * d2 : fabsf(d2) - 0.5f;
        float s3 = fabsf(d3) < 1.f ? 0.5f * d3 * d3 : fabsf(d3) - 0.5f;
        regv = s0 + s1 + s2 + s3;
    }

    float pcx = acx + o0 * aw, pcy = acy + o1 * ah;
    float pw = aw * expf(o2), ph = ah * expf(o3);
    float* pr = out + 1 + (size_t)gid * 4;
    pr[0] = (pcx - pw * 0.5f) * posf;
    pr[1] = (pcy - ph * 0.5f) * posf;
    pr[2] = (pcx + pw * 0.5f) * posf;
    pr[3] = (pcy + ph * 0.5f) * posf;
    out[1 + (size_t)BB * NN * 4 + gid] = posf;

    redc[tid] = clsv; redr[tid] = regv;
    __syncthreads();
    for (int s = 128; s > 0; s >>= 1) {
        if (tid < s) { redc[tid] += redc[tid + s]; redr[tid] += redr[tid + s]; }
        __syncthreads();
    }
    if (tid == 0) { g_clsp[blockIdx.x] = redc[0]; g_regp[blockIdx.x] = redr[0]; }
}

/* ============ kernel 5: finalize scalar loss ============================ */
__global__ void k_fin(float* __restrict__ out) {
    float c = 0.f, r = 0.f;
    for (int i = 0; i < 144; i++) { c += g_clsp[i]; r += g_regp[i]; }
    out[0] = (c + 5.f * r) * 0.25f;
}

/* ============ launch ==================================================== */
extern "C" void kernel_launch(void* const* d_in, const int* in_sizes, int n_in,
                              void* d_out, int out_size) {
    const float* fm  = (const float*)d_in[0];
    const float* gtb = (const float*)d_in[1];
    const float* w1  = (const float*)d_in[3];
    const float* b1  = (const float*)d_in[4];
    const float* cw  = (const float*)d_in[5];
    const float* cb  = (const float*)d_in[6];
    const float* rw  = (const float*)d_in[7];
    const float* rb  = (const float*)d_in[8];
    float* out = (float*)d_out;

    static int smem_set = 0;
    if (!smem_set) {
        cudaFuncSetAttribute(k_convmma, cudaFuncAttributeMaxDynamicSharedMemorySize,
                             SMEM_BYTES);
        smem_set = 1;
    }

    k_convmma<<<dim3(32, 4), 256, SMEM_BYTES>>>(fm, w1, b1);
    k_heads<<<32, 256>>>(cw, cb, rw, rb);
    k_maxpg<<<BB * GG, 256>>>(gtb);
    k_loss<<<144, 256>>>(gtb, out);
    k_fin<<<1, 1>>>(out);
}

// round 8
// speedup vs baseline: 1.8681x; 1.3799x over previous
#include <cuda_runtime.h>
#include <cstdint>

typedef unsigned int u32;

#define BB 4
#define HID 512
#define GG 20
#define NN (32*32*9)
#define MM (4*32*32)
#define KK (2048*9)
#define KT 32
#define KTILES (KK/KT)          /* 576 */
#define SAS 136                 /* A smem stride (floats): bank 8t+g conflict-free */
#define SBK 36                  /* B smem stride (floats): bank 4g+t conflict-free */
#define STAGE_FLOATS (KT*SAS + 128*SBK)   /* 4352 + 4608 = 8960 */
#define SMEM_BYTES (3*STAGE_FLOATS*4)     /* 107520 */
#define PADP 1156               /* 34*34 padded plane */
#define NPAD (4*2048*PADP)      /* 9469952 */
#define NWR (512*18432)         /* 9437184 */
#define EPSF 1e-8f

/* ---------------- scratch (static device globals; no allocation) ------- */
__device__ float g_fmp[NPAD];                 /* padded + tf32-rounded input */
__device__ float g_wr[NWR];                   /* tf32-rounded conv1 weights  */
__device__ float g_hid[MM * HID];             /* relu(conv1) pixel-major     */
__device__ float g_po[MM * 45];               /* per pixel: 9 conf + 36 reg  */
__device__ float g_maxpg[BB * GG];
__device__ float g_clsp[144];
__device__ float g_regp[144];

/* ---------------- helpers ---------------------------------------------- */
__device__ __forceinline__ u32 s2u(const void* p) {
    u32 a;
    asm("{ .reg .u64 t; cvta.to.shared.u64 t, %1; cvt.u32.u64 %0, t; }" : "=r"(a) : "l"(p));
    return a;
}
__device__ __forceinline__ float tf32r(float x) {
    float r; asm("cvt.rna.tf32.f32 %0, %1;" : "=f"(r) : "f"(x)); return r;
}
__device__ __forceinline__ void cpa4(u32 dst, const float* src) {
    asm volatile("cp.async.ca.shared.global [%0], [%1], 4;" :: "r"(dst), "l"(src));
}
__device__ __forceinline__ void cpa16(u32 dst, const float* src) {
    asm volatile("cp.async.cg.shared.global [%0], [%1], 16;" :: "r"(dst), "l"(src));
}
#define CP_COMMIT() asm volatile("cp.async.commit_group;" ::: "memory")
#define CP_WAIT1()  asm volatile("cp.async.wait_group 1;" ::: "memory")

__device__ __forceinline__ void mma_tf32(float& d0, float& d1, float& d2, float& d3,
                                         u32 a0, u32 a1, u32 a2, u32 a3,
                                         u32 b0, u32 b1) {
    asm volatile(
        "mma.sync.aligned.m16n8k8.row.col.f32.tf32.tf32.f32 "
        "{%0,%1,%2,%3}, {%4,%5,%6,%7}, {%8,%9}, {%0,%1,%2,%3};"
        : "+f"(d0), "+f"(d1), "+f"(d2), "+f"(d3)
        : "r"(a0), "r"(a1), "r"(a2), "r"(a3), "r"(b0), "r"(b1));
}
__device__ __forceinline__ float softplusf(float z) {
    return fmaxf(z, 0.f) + log1pf(expf(-fabsf(z)));
}
__device__ __forceinline__ void anchor_of(int n, float& x1, float& y1, float& x2,
                                          float& y2, float& areaA) {
    int cell = n / 9;  int a = n - cell * 9;
    int yI = cell >> 5, xI = cell & 31;
    int s = a / 3;     int r = a - s * 3;
    float aw = (float)(2 * (s + 1));
    float ah = __fmul_rn(aw, 0.5f + 0.5f * (float)r);
    float xc = (float)xI + 0.5f, yc = (float)yI + 0.5f;
    float hx = __fmul_rn(0.5f, aw), hy = __fmul_rn(0.5f, ah);
    x1 = fminf(fmaxf(__fsub_rn(xc, hx), 0.f), 32.f);
    y1 = fminf(fmaxf(__fsub_rn(yc, hy), 0.f), 32.f);
    x2 = fminf(fmaxf(__fadd_rn(xc, hx), 0.f), 32.f);
    y2 = fminf(fmaxf(__fadd_rn(yc, hy), 0.f), 32.f);
    areaA = __fmul_rn(__fsub_rn(x2, x1), __fsub_rn(y2, y1));
}
__device__ __forceinline__ float iou_f(float ax1, float ay1, float ax2, float ay2,
                                       float areaA, float gx1, float gy1, float gx2,
                                       float gy2, float areaG) {
    float lx = fmaxf(ax1, gx1), ly = fmaxf(ay1, gy1);
    float rx = fminf(ax2, gx2), ry = fminf(ay2, gy2);
    float iw = fmaxf(__fsub_rn(rx, lx), 0.f);
    float ih = fmaxf(__fsub_rn(ry, ly), 0.f);
    float inter = __fmul_rn(iw, ih);
    float den = __fadd_rn(__fsub_rn(__fadd_rn(areaA, areaG), inter), EPSF);
    return __fdiv_rn(inter, den);
}

/* ============ kernel 0a: pad + tf32-round feature map =================== */
__global__ __launch_bounds__(256) void k_pad(const float* __restrict__ fm) {
    int i = blockIdx.x * 256 + threadIdx.x;       /* < NPAD exactly */
    int p = i % PADP;  int pc = i / PADP;         /* pc = b*2048 + c */
    int py = p / 34, px = p - py * 34;
    float v = 0.f;
    if (py >= 1 && py <= 32 && px >= 1 && px <= 32)
        v = tf32r(__ldg(fm + ((size_t)pc << 10) + ((py - 1) << 5) + (px - 1)));
    g_fmp[i] = v;
}
/* ============ kernel 0b: tf32-round conv1 weights ======================= */
__global__ __launch_bounds__(256) void k_wrnd(const float* __restrict__ w1) {
    int i = blockIdx.x * 256 + threadIdx.x;       /* < NWR exactly (float4) */
    float4 x = __ldg((const float4*)w1 + i);
    ((float4*)g_wr)[i] = make_float4(tf32r(x.x), tf32r(x.y), tf32r(x.z), tf32r(x.w));
}

/* ============ kernel 1: conv1, cp.async 3-stage pipelined tf32 MMA ====== */
/* GEMM M=4096 N=512 K=18432. CTA 128x128xKT32, grid (32,4), 256 thr.      */
__global__ __launch_bounds__(256, 1) void k_convmma(const float* __restrict__ b1) {
    extern __shared__ float sm[];
    const u32 sm0 = s2u(sm);
    const int tid = threadIdx.x;
    const int lane = tid & 31, wid = tid >> 5;
    const int g = lane >> 2, tig = lane & 3;
    const int wm = wid >> 2, wn = wid & 3;        /* warp grid 2x4, tile 64x32 */
    const int m0 = blockIdx.x * 128, n0 = blockIdx.y * 128;
    const int mloc = tid & 127, kh = tid >> 7;    /* producer role */

    const int m = m0 + mloc;
    const int bbi = m >> 10, y0 = (m >> 5) & 31, x0 = m & 31;
    const long Abase = (long)(bbi * 2048) * PADP + y0 * 34 + x0;

    float acc[4][4][4];
#pragma unroll
    for (int i = 0; i < 4; i++)
#pragma unroll
        for (int j = 0; j < 4; j++)
#pragma unroll
            for (int c = 0; c < 4; c++) acc[i][j][c] = 0.f;

    /* issue one K-stage's copies into smem stage slot s */
#define ISSUE(it, s) do {                                                      \
        int kb = (it) * KT;                                                    \
        u32 aB = sm0 + (u32)((s) * STAGE_FLOATS) * 4;                          \
        u32 bB = aB + KT * SAS * 4;                                            \
        _Pragma("unroll")                                                      \
        for (int q = 0; q < 4; q++) {                                          \
            int ci = tid + q * 256;                                            \
            int oc = ci >> 3, kq = ci & 7;                                     \
            cpa16(bB + (u32)(oc * SBK + kq * 4) * 4,                           \
                  g_wr + (size_t)(n0 + oc) * KK + kb + kq * 4);                \
        }                                                                      \
        _Pragma("unroll")                                                      \
        for (int q = 0; q < 16; q++) {                                         \
            int kloc = 2 * q + kh;                                             \
            int kg = kb + kloc;                                                \
            int dc = kg / 9, t9 = kg - 9 * dc;                                 \
            int yq = t9 / 3, xr = t9 - 3 * yq;                                 \
            cpa4(aB + (u32)(kloc * SAS + mloc) * 4,                            \
                 g_fmp + Abase + dc * PADP + yq * 34 + xr);                    \
        }                                                                      \
    } while (0)

    ISSUE(0, 0); CP_COMMIT();
    ISSUE(1, 1); CP_COMMIT();

    for (int it = 0; it < KTILES; it++) {
        CP_WAIT1();
        __syncthreads();
        const int s = it % 3;
        if (it + 2 < KTILES) { ISSUE(it + 2, (it + 2) % 3); }
        CP_COMMIT();

        const float* As = sm + s * STAGE_FLOATS;
        const float* Bs = As + KT * SAS;
#pragma unroll
        for (int ks = 0; ks < 4; ks++) {
            const int kk = ks * 8 + tig;
            const float* Ak = As + kk * SAS + wm * 64 + g;
            u32 af[4][4], bf2[4][2];
#pragma unroll
            for (int i = 0; i < 4; i++) {
                af[i][0] = __float_as_uint(Ak[i * 16]);
                af[i][1] = __float_as_uint(Ak[i * 16 + 8]);
                af[i][2] = __float_as_uint(Ak[i * 16 + 4 * SAS]);
                af[i][3] = __float_as_uint(Ak[i * 16 + 8 + 4 * SAS]);
            }
#pragma unroll
            for (int j = 0; j < 4; j++) {
                int nn = wn * 32 + j * 8 + g;
                bf2[j][0] = __float_as_uint(Bs[nn * SBK + kk]);
                bf2[j][1] = __float_as_uint(Bs[nn * SBK + kk + 4]);
            }
#pragma unroll
            for (int i = 0; i < 4; i++)
#pragma unroll
                for (int j = 0; j < 4; j++)
                    mma_tf32(acc[i][j][0], acc[i][j][1], acc[i][j][2], acc[i][j][3],
                             af[i][0], af[i][1], af[i][2], af[i][3],
                             bf2[j][0], bf2[j][1]);
        }
    }

    /* ---- epilogue: bias + relu -> g_hid ---- */
#pragma unroll
    for (int j = 0; j < 4; j++) {
        int nb = n0 + wn * 32 + j * 8 + 2 * tig;
        float bb0 = b1[nb], bb1 = b1[nb + 1];
#pragma unroll
        for (int i = 0; i < 4; i++) {
            int ma = m0 + wm * 64 + i * 16 + g;
            float2* d0 = (float2*)(g_hid + (size_t)ma * 512 + nb);
            float2* d1 = (float2*)(g_hid + (size_t)(ma + 8) * 512 + nb);
            *d0 = make_float2(fmaxf(acc[i][j][0] + bb0, 0.f),
                              fmaxf(acc[i][j][1] + bb1, 0.f));
            *d1 = make_float2(fmaxf(acc[i][j][2] + bb0, 0.f),
                              fmaxf(acc[i][j][3] + bb1, 0.f));
        }
    }
#undef ISSUE
}

/* ============ kernel 2: 1x1 heads (conf 9 + reg 36) ===================== */
__global__ __launch_bounds__(256) void k_heads(const float* __restrict__ cw,
                                               const float* __restrict__ cb,
                                               const float* __restrict__ rw,
                                               const float* __restrict__ rb) {
    __shared__ float As[128][33];
    __shared__ float Bs[32][48];
    int tid = threadIdx.x;
    int m0 = blockIdx.x * 128;
    int tx = tid & 15, ty = tid >> 4;
    float acc[8][3] = {};
    for (int k0 = 0; k0 < 512; k0 += 32) {
#pragma unroll
        for (int i = 0; i < 16; i++) {
            int idx = i * 256 + tid;
            int mmi = idx >> 5, kki = idx & 31;
            As[mmi][kki] = g_hid[(size_t)(m0 + mmi) * 512 + k0 + kki];
        }
#pragma unroll
        for (int i = 0; i < 6; i++) {
            int idx = i * 256 + tid;
            int kki = idx / 48, nn = idx - kki * 48;
            float v = 0.f;
            if (nn < 9)       v = cw[nn * 512 + k0 + kki];
            else if (nn < 45) v = rw[(nn - 9) * 512 + k0 + kki];
            Bs[kki][nn] = v;
        }
        __syncthreads();
#pragma unroll
        for (int kki = 0; kki < 32; kki++) {
            float a[8], b3[3];
#pragma unroll
            for (int i = 0; i < 8; i++) a[i] = As[ty * 8 + i][kki];
#pragma unroll
            for (int j = 0; j < 3; j++) b3[j] = Bs[kki][tx * 3 + j];
#pragma unroll
            for (int i = 0; i < 8; i++)
#pragma unroll
                for (int j = 0; j < 3; j++) acc[i][j] += a[i] * b3[j];
        }
        __syncthreads();
    }
#pragma unroll
    for (int i = 0; i < 8; i++)
#pragma unroll
        for (int j = 0; j < 3; j++) {
            int n = tx * 3 + j;
            if (n < 45) {
                float bias = (n < 9) ? cb[n] : rb[n - 9];
                g_po[(size_t)(m0 + ty * 8 + i) * 45 + n] = acc[i][j] + bias;
            }
        }
}

/* ============ kernel 3: max IoU per (b,g) =============================== */
__global__ void k_maxpg(const float* __restrict__ gtb) {
    int b = blockIdx.x / GG, g = blockIdx.x % GG;
    int tid = threadIdx.x;
    float gx1 = __fmul_rn(gtb[(b * GG + g) * 4 + 0], 0.03125f);
    float gy1 = __fmul_rn(gtb[(b * GG + g) * 4 + 1], 0.03125f);
    float gx2 = __fmul_rn(gtb[(b * GG + g) * 4 + 2], 0.03125f);
    float gy2 = __fmul_rn(gtb[(b * GG + g) * 4 + 3], 0.03125f);
    float areaG = __fmul_rn(__fsub_rn(gx2, gx1), __fsub_rn(gy2, gy1));
    float mx = 0.f;
    for (int n = tid; n < NN; n += 256) {
        float x1, y1, x2, y2, aA;
        anchor_of(n, x1, y1, x2, y2, aA);
        mx = fmaxf(mx, iou_f(x1, y1, x2, y2, aA, gx1, gy1, gx2, gy2, areaG));
    }
    __shared__ float red[256];
    red[tid] = mx;
    __syncthreads();
    for (int s = 128; s > 0; s >>= 1) {
        if (tid < s) red[tid] = fmaxf(red[tid], red[tid + s]);
        __syncthreads();
    }
    if (tid == 0) g_maxpg[blockIdx.x] = red[0];
}

/* ============ kernel 4: assign + losses + proposals ===================== */
__global__ void k_loss(const float* __restrict__ gtb, float* __restrict__ out) {
    __shared__ float sg[GG][4], sArea[GG], sMpg[GG];
    __shared__ float redc[256], redr[256];
    int tid = threadIdx.x;
    int b = blockIdx.x / 36;
    int gid = blockIdx.x * 256 + tid;
    int n = gid - b * NN;

    if (tid < 80) sg[tid >> 2][tid & 3] = __fmul_rn(gtb[b * 80 + tid], 0.03125f);
    __syncthreads();
    if (tid < GG) {
        sArea[tid] = __fmul_rn(__fsub_rn(sg[tid][2], sg[tid][0]),
                               __fsub_rn(sg[tid][3], sg[tid][1]));
        sMpg[tid] = g_maxpg[b * GG + tid];
    }
    __syncthreads();

    float x1, y1, x2, y2, aA;
    anchor_of(n, x1, y1, x2, y2, aA);

    float maxi = -1e30f; int gi = 0; bool pos = false;
#pragma unroll
    for (int g = 0; g < GG; g++) {
        float io = iou_f(x1, y1, x2, y2, aA, sg[g][0], sg[g][1], sg[g][2], sg[g][3],
                         sArea[g]);
        if (io > 0.7f) pos = true;
        if (io == sMpg[g] && sMpg[g] > EPSF) pos = true;
        if (io > maxi) { maxi = io; gi = g; }
    }
    bool neg = (maxi < 0.3f) && !pos;
    float posf = pos ? 1.f : 0.f;

    float gx1 = sg[gi][0], gy1 = sg[gi][1], gx2 = sg[gi][2], gy2 = sg[gi][3];

    float acx = (x1 + x2) * 0.5f, acy = (y1 + y2) * 0.5f;
    float aw = x2 - x1, ah = y2 - y1;
    float gcx = (gx1 + gx2) * 0.5f, gcy = (gy1 + gy2) * 0.5f;
    float gw = gx2 - gx1, gh = gy2 - gy1;
    float t0 = (gcx - acx) / (aw + EPSF);
    float t1 = (gcy - acy) / (ah + EPSF);
    float t2 = logf((gw + EPSF) / (aw + EPSF));
    float t3 = logf((gh + EPSF) / (ah + EPSF));

    int cell = n / 9; int a = n - cell * 9;
    size_t pb = (size_t)(b * 1024 + cell) * 45;
    float conf = g_po[pb + a];
    float o0 = g_po[pb + 9 + a * 4 + 0];
    float o1 = g_po[pb + 9 + a * 4 + 1];
    float o2 = g_po[pb + 9 + a * 4 + 2];
    float o3 = g_po[pb + 9 + a * 4 + 3];

    float clsv = pos ? softplusf(-conf) : (neg ? softplusf(conf) : 0.f);
    float regv = 0.f;
    if (pos) {
        float d0 = o0 - t0, d1 = o1 - t1, d2 = o2 - t2, d3 = o3 - t3;
        float s0 = fabsf(d0) < 1.f ? 0.5f * d0 * d0 : fabsf(d0) - 0.5f;
        float s1 = fabsf(d1) < 1.f ? 0.5f * d1 * d1 : fabsf(d1) - 0.5f;
        float s2 = fabsf(d2) < 1.f ? 0.5f * d2 * d2 : fabsf(d2) - 0.5f;
        float s3 = fabsf(d3) < 1.f ? 0.5f * d3 * d3 : fabsf(d3) - 0.5f;
        regv = s0 + s1 + s2 + s3;
    }

    float pcx = acx + o0 * aw, pcy = acy + o1 * ah;
    float pw = aw * expf(o2), ph = ah * expf(o3);
    float* pr = out + 1 + (size_t)gid * 4;
    pr[0] = (pcx - pw * 0.5f) * posf;
    pr[1] = (pcy - ph * 0.5f) * posf;
    pr[2] = (pcx + pw * 0.5f) * posf;
    pr[3] = (pcy + ph * 0.5f) * posf;
    out[1 + (size_t)BB * NN * 4 + gid] = posf;

    redc[tid] = clsv; redr[tid] = regv;
    __syncthreads();
    for (int s = 128; s > 0; s >>= 1) {
        if (tid < s) { redc[tid] += redc[tid + s]; redr[tid] += redr[tid + s]; }
        __syncthreads();
    }
    if (tid == 0) { g_clsp[blockIdx.x] = redc[0]; g_regp[blockIdx.x] = redr[0]; }
}

/* ============ kernel 5: finalize scalar loss ============================ */
__global__ void k_fin(float* __restrict__ out) {
    float c = 0.f, r = 0.f;
    for (int i = 0; i < 144; i++) { c += g_clsp[i]; r += g_regp[i]; }
    out[0] = (c + 5.f * r) * 0.25f;
}

/* ============ launch ==================================================== */
extern "C" void kernel_launch(void* const* d_in, const int* in_sizes, int n_in,
                              void* d_out, int out_size) {
    const float* fm  = (const float*)d_in[0];
    const float* gtb = (const float*)d_in[1];
    const float* w1  = (const float*)d_in[3];
    const float* b1  = (const float*)d_in[4];
    const float* cw  = (const float*)d_in[5];
    const float* cb  = (const float*)d_in[6];
    const float* rw  = (const float*)d_in[7];
    const float* rb  = (const float*)d_in[8];
    float* out = (float*)d_out;

    cudaFuncSetAttribute(k_convmma, cudaFuncAttributeMaxDynamicSharedMemorySize,
                         SMEM_BYTES);

    k_pad<<<NPAD / 256, 256>>>(fm);
    k_wrnd<<<NWR / 4 / 256, 256>>>(w1);
    k_convmma<<<dim3(32, 4), 256, SMEM_BYTES>>>(b1);
    k_heads<<<32, 256>>>(cw, cb, rw, rb);
    k_maxpg<<<BB * GG, 256>>>(gtb);
    k_loss<<<144, 256>>>(gtb, out);
    k_fin<<<1, 1>>>(out);
}

// round 10
// speedup vs baseline: 2.0707x; 1.1085x over previous
#include <cuda_runtime.h>
#include <cstdint>

typedef unsigned int u32;

#define BB 4
#define HID 512
#define GG 20
#define NN (32*32*9)
#define MM (4*32*32)
#define KK (2048*9)
#define KTILES 576              /* 9 taps x 64 channel-chunks of 32 */
#define SAS 36                  /* A smem stride: bank 4m+k conflict-free */
#define ST_A 4608               /* 128*36 floats */
#define ST_B 4608               /* 4 wn * 32 lanes * 36 floats (fragment-packed) */
#define STF (ST_A + ST_B)       /* 9216 floats per stage */
#define SMEM_BYTES (3*STF*4)    /* 110592 */
#define NFMT (MM*2048)          /* 8388608 */
#define NWF (512*18432)         /* 9437184 */
#define EPSF 1e-8f

/* ---------------- scratch (static device globals; no allocation) ------- */
__device__ float g_fmt[NFMT];                 /* pixel-major tf32 input [b,y,x,c] */
__device__ float g_wf[NWF];                   /* fragment-packed tf32 weights     */
__device__ float g_hid[MM * HID];             /* relu(conv1) pixel-major          */
__device__ float g_po[MM * 45];               /* per pixel: 9 conf + 36 reg       */
__device__ float g_maxpg[BB * GG];
__device__ float g_clsp[144];
__device__ float g_regp[144];

/* ---------------- helpers ---------------------------------------------- */
__device__ __forceinline__ u32 s2u(const void* p) {
    u32 a;
    asm("{ .reg .u64 t; cvta.to.shared.u64 t, %1; cvt.u32.u64 %0, t; }" : "=r"(a) : "l"(p));
    return a;
}
__device__ __forceinline__ float tf32r(float x) {
    float r; asm("cvt.rna.tf32.f32 %0, %1;" : "=f"(r) : "f"(x)); return r;
}
__device__ __forceinline__ void cpa16(u32 dst, const float* src) {
    asm volatile("cp.async.cg.shared.global [%0], [%1], 16;" :: "r"(dst), "l"(src));
}
__device__ __forceinline__ void cpa16z(u32 dst, const float* src, int srcsize) {
    asm volatile("cp.async.cg.shared.global [%0], [%1], 16, %2;"
                 :: "r"(dst), "l"(src), "r"(srcsize));
}
#define CP_COMMIT() asm volatile("cp.async.commit_group;" ::: "memory")
#define CP_WAIT1()  asm volatile("cp.async.wait_group 1;" ::: "memory")

__device__ __forceinline__ void mma_tf32(float& d0, float& d1, float& d2, float& d3,
                                         u32 a0, u32 a1, u32 a2, u32 a3,
                                         u32 b0, u32 b1) {
    asm volatile(
        "mma.sync.aligned.m16n8k8.row.col.f32.tf32.tf32.f32 "
        "{%0,%1,%2,%3}, {%4,%5,%6,%7}, {%8,%9}, {%0,%1,%2,%3};"
        : "+f"(d0), "+f"(d1), "+f"(d2), "+f"(d3)
        : "r"(a0), "r"(a1), "r"(a2), "r"(a3), "r"(b0), "r"(b1));
}
__device__ __forceinline__ float softplusf(float z) {
    return fmaxf(z, 0.f) + log1pf(expf(-fabsf(z)));
}
__device__ __forceinline__ void anchor_of(int n, float& x1, float& y1, float& x2,
                                          float& y2, float& areaA) {
    int cell = n / 9;  int a = n - cell * 9;
    int yI = cell >> 5, xI = cell & 31;
    int s = a / 3;     int r = a - s * 3;
    float aw = (float)(2 * (s + 1));
    float ah = __fmul_rn(aw, 0.5f + 0.5f * (float)r);
    float xc = (float)xI + 0.5f, yc = (float)yI + 0.5f;
    float hx = __fmul_rn(0.5f, aw), hy = __fmul_rn(0.5f, ah);
    x1 = fminf(fmaxf(__fsub_rn(xc, hx), 0.f), 32.f);
    y1 = fminf(fmaxf(__fsub_rn(yc, hy), 0.f), 32.f);
    x2 = fminf(fmaxf(__fadd_rn(xc, hx), 0.f), 32.f);
    y2 = fminf(fmaxf(__fadd_rn(yc, hy), 0.f), 32.f);
    areaA = __fmul_rn(__fsub_rn(x2, x1), __fsub_rn(y2, y1));
}
__device__ __forceinline__ float iou_f(float ax1, float ay1, float ax2, float ay2,
                                       float areaA, float gx1, float gy1, float gx2,
                                       float gy2, float areaG) {
    float lx = fmaxf(ax1, gx1), ly = fmaxf(ay1, gy1);
    float rx = fminf(ax2, gx2), ry = fminf(ay2, gy2);
    float iw = fmaxf(__fsub_rn(rx, lx), 0.f);
    float ih = fmaxf(__fsub_rn(ry, ly), 0.f);
    float inter = __fmul_rn(iw, ih);
    float den = __fadd_rn(__fsub_rn(__fadd_rn(areaA, areaG), inter), EPSF);
    return __fdiv_rn(inter, den);
}

/* ============ kernel 0a: transpose fm to pixel-major + tf32 round ======= */
/* grid (32 pixblk, 64 cblk, 4 b), block (32,8) */
__global__ __launch_bounds__(256) void k_fmt(const float* __restrict__ fm) {
    __shared__ float t[32][33];
    int pb = blockIdx.x * 32, cb = blockIdx.y * 32, b = blockIdx.z;
    int tx = threadIdx.x, ty = threadIdx.y;
#pragma unroll
    for (int i = ty; i < 32; i += 8)
        t[i][tx] = tf32r(__ldg(fm + ((size_t)(b * 2048 + cb + i) << 10) + pb + tx));
    __syncthreads();
#pragma unroll
    for (int i = ty; i < 32; i += 8)
        g_fmt[(((size_t)(b * 1024 + pb + i)) << 11) + cb + tx] = t[tx][i];
}

/* ============ kernel 0b: repack weights into mma-fragment order ========= */
/* grid (64 cblk, 16 nblk), 256 thr. K-order tap-major: kglob = t*2048 + c */
__global__ __launch_bounds__(256) void k_wpack(const float* __restrict__ w1) {
    __shared__ float s[32][289];
    int cb = blockIdx.x;               /* channel block: c0 = cb*32 */
    int nb = blockIdx.y;               /* n block: n0b = nb*32 */
    int n0b = nb * 32;
    int nt = nb >> 2, wn = nb & 3;
    int tid = threadIdx.x;
    /* load 32 n-rows x 288 contiguous floats (c0*9 .. c0*9+288) */
    for (int idx = tid; idx < 32 * 288; idx += 256) {
        int r = idx / 288, cc = idx - r * 288;
        s[r][cc] = tf32r(__ldg(w1 + (size_t)(n0b + r) * KK + cb * 288 + cc));
    }
    __syncthreads();
    /* emit 9 taps x 1024 fragment-ordered floats */
    for (int t = 0; t < 9; t++) {
        size_t base = ((size_t)((nt * 576 + t * 64 + cb) * 4 + wn)) << 10;
#pragma unroll
        for (int q = 0; q < 4; q++) {
            int o = q * 256 + tid;
            int inner = o & 31;
            int ks = inner >> 3, j = (inner >> 1) & 3, h = inner & 1;
            int lane = o >> 5;
            int g = lane >> 2, tig = lane & 3;
            int klocal = ks * 8 + tig + 4 * h;
            int nloc = j * 8 + g;
            g_wf[base + o] = s[nloc][klocal * 9 + t];
        }
    }
}

/* ============ kernel 1: conv1, tap-GEMM cp.async pipelined tf32 MMA ===== */
/* M=4096 N=512; K iterated as 9 taps x 64 chunks of 32 ch. grid (32,4).   */
__global__ __launch_bounds__(256, 1) void k_convmma(const float* __restrict__ b1) {
    extern __shared__ float sm[];
    const u32 sm0 = s2u(sm);
    const int tid = threadIdx.x;
    const int lane = tid & 31, wid = tid >> 5;
    const int g = lane >> 2, tig = lane & 3;
    const int wm = wid >> 2, wn = wid & 3;        /* warp grid 2x4, tile 64x32 */
    const int m0 = blockIdx.x * 128;
    const int nt = blockIdx.y;                     /* n0 = nt*128 */

    /* producer roles */
    const int pp = tid >> 1, hh16 = (tid & 1) * 16;
    const int mp = m0 + pp;
    const int bbp = mp >> 10, yp = (mp >> 5) & 31, xp = mp & 31;

    float acc[4][4][4];
#pragma unroll
    for (int i = 0; i < 4; i++)
#pragma unroll
        for (int j = 0; j < 4; j++)
#pragma unroll
            for (int c = 0; c < 4; c++) acc[i][j][c] = 0.f;

#define ISSUE(it, s) do {                                                      \
        int tap = (it) >> 6;                                                   \
        int c0 = ((it) & 63) << 5;                                             \
        u32 aB = sm0 + (u32)((s) * STF) * 4;                                   \
        u32 bB = aB + (u32)ST_A * 4;                                           \
        {   /* B: contiguous fragment-packed 4096 floats */                    \
            const float* srcB = g_wf + (((size_t)(nt * 576 + (it))) << 12)     \
                                + tid * 16;                                    \
            u32 dB = bB + (u32)((tid >> 1) * 36 + (tid & 1) * 16) * 4;         \
            cpa16(dB, srcB);       cpa16(dB + 16, srcB + 4);                   \
            cpa16(dB + 32, srcB + 8); cpa16(dB + 48, srcB + 12);               \
        }                                                                      \
        {   /* A: 32 channels of shifted pixel, zfill off-edge */              \
            int dy = tap / 3 - 1, dx = tap - (tap / 3) * 3 - 1;                \
            int yy = yp + dy, xx = xp + dx;                                    \
            int vs = ((unsigned)yy < 32u && (unsigned)xx < 32u) ? 16 : 0;      \
            const float* srcA = vs ? g_fmt +                                   \
                ((((size_t)(bbp << 10) + (yy << 5) + xx)) << 11) + c0 + hh16   \
                : g_fmt;                                                       \
            u32 dA = aB + (u32)(pp * 36 + hh16) * 4;                           \
            cpa16z(dA, srcA, vs);       cpa16z(dA + 16, srcA + 4, vs);         \
            cpa16z(dA + 32, srcA + 8, vs); cpa16z(dA + 48, srcA + 12, vs);     \
        }                                                                      \
    } while (0)

    ISSUE(0, 0); CP_COMMIT();
    ISSUE(1, 1); CP_COMMIT();

    for (int it = 0; it < KTILES; it++) {
        CP_WAIT1();
        __syncthreads();
        const int s = it % 3;
        if (it + 2 < KTILES) ISSUE(it + 2, (it + 2) % 3);
        CP_COMMIT();

        const float* As = sm + s * STF;
        const float4* Bf = (const float4*)(As + ST_A) + (size_t)(wn * 32 + lane) * 9;
        const float* Ab0 = As + (wm * 64 + g) * 36 + tig;
#pragma unroll
        for (int ks = 0; ks < 4; ks++) {
            float4 bA = Bf[ks * 2], bBv = Bf[ks * 2 + 1];
            const float* Ab = Ab0 + ks * 8;
#pragma unroll
            for (int i = 0; i < 4; i++) {
                u32 a0 = __float_as_uint(Ab[i * 576]);
                u32 a1 = __float_as_uint(Ab[i * 576 + 288]);
                u32 a2 = __float_as_uint(Ab[i * 576 + 4]);
                u32 a3 = __float_as_uint(Ab[i * 576 + 292]);
                mma_tf32(acc[i][0][0], acc[i][0][1], acc[i][0][2], acc[i][0][3],
                         a0, a1, a2, a3, __float_as_uint(bA.x), __float_as_uint(bA.y));
                mma_tf32(acc[i][1][0], acc[i][1][1], acc[i][1][2], acc[i][1][3],
                         a0, a1, a2, a3, __float_as_uint(bA.z), __float_as_uint(bA.w));
                mma_tf32(acc[i][2][0], acc[i][2][1], acc[i][2][2], acc[i][2][3],
                         a0, a1, a2, a3, __float_as_uint(bBv.x), __float_as_uint(bBv.y));
                mma_tf32(acc[i][3][0], acc[i][3][1], acc[i][3][2], acc[i][3][3],
                         a0, a1, a2, a3, __float_as_uint(bBv.z), __float_as_uint(bBv.w));
            }
        }
    }
#undef ISSUE

    /* ---- epilogue: bias + relu -> g_hid ---- */
#pragma unroll
    for (int j = 0; j < 4; j++) {
        int nb = nt * 128 + wn * 32 + j * 8 + 2 * tig;
        float bb0 = b1[nb], bb1 = b1[nb + 1];
#pragma unroll
        for (int i = 0; i < 4; i++) {
            int ma = m0 + wm * 64 + i * 16 + g;
            float2* d0 = (float2*)(g_hid + (size_t)ma * 512 + nb);
            float2* d1 = (float2*)(g_hid + (size_t)(ma + 8) * 512 + nb);
            *d0 = make_float2(fmaxf(acc[i][j][0] + bb0, 0.f),
                              fmaxf(acc[i][j][1] + bb1, 0.f));
            *d1 = make_float2(fmaxf(acc[i][j][2] + bb0, 0.f),
                              fmaxf(acc[i][j][3] + bb1, 0.f));
        }
    }
}

/* ============ kernel 2: 1x1 heads, M-tile 32, grid 128 ================== */
__global__ __launch_bounds__(256) void k_heads(const float* __restrict__ cw,
                                               const float* __restrict__ cb,
                                               const float* __restrict__ rw,
                                               const float* __restrict__ rb) {
    __shared__ float As[32][33];
    __shared__ float Bs[32][48];
    int tid = threadIdx.x;
    int m0 = blockIdx.x * 32;
    int tx = tid & 15, ty = tid >> 4;
    float acc[2][3] = {};
    for (int k0 = 0; k0 < 512; k0 += 32) {
#pragma unroll
        for (int i = 0; i < 4; i++) {
            int idx = i * 256 + tid;
            int mmi = idx >> 5, kki = idx & 31;
            As[mmi][kki] = g_hid[(size_t)(m0 + mmi) * 512 + k0 + kki];
        }
#pragma unroll
        for (int i = 0; i < 6; i++) {
            int idx = i * 256 + tid;
            int kki = idx / 48, nn = idx - kki * 48;
            float v = 0.f;
            if (nn < 9)       v = cw[nn * 512 + k0 + kki];
            else if (nn < 45) v = rw[(nn - 9) * 512 + k0 + kki];
            Bs[kki][nn] = v;
        }
        __syncthreads();
#pragma unroll
        for (int kki = 0; kki < 32; kki++) {
            float a0 = As[ty][kki], a1 = As[ty + 16][kki];
            float b3[3];
#pragma unroll
            for (int j = 0; j < 3; j++) b3[j] = Bs[kki][tx * 3 + j];
#pragma unroll
            for (int j = 0; j < 3; j++) {
                acc[0][j] += a0 * b3[j];
                acc[1][j] += a1 * b3[j];
            }
        }
        __syncthreads();
    }
#pragma unroll
    for (int p = 0; p < 2; p++)
#pragma unroll
        for (int j = 0; j < 3; j++) {
            int n = tx * 3 + j;
            if (n < 45) {
                float bias = (n < 9) ? cb[n] : rb[n - 9];
                g_po[(size_t)(m0 + ty + 16 * p) * 45 + n] = acc[p][j] + bias;
            }
        }
}

/* ============ kernel 3: max IoU per (b,g) =============================== */
__global__ void k_maxpg(const float* __restrict__ gtb) {
    int b = blockIdx.x / GG, g = blockIdx.x % GG;
    int tid = threadIdx.x;
    float gx1 = __fmul_rn(gtb[(b * GG + g) * 4 + 0], 0.03125f);
    float gy1 = __fmul_rn(gtb[(b * GG + g) * 4 + 1], 0.03125f);
    float gx2 = __fmul_rn(gtb[(b * GG + g) * 4 + 2], 0.03125f);
    float gy2 = __fmul_rn(gtb[(b * GG + g) * 4 + 3], 0.03125f);
    float areaG = __fmul_rn(__fsub_rn(gx2, gx1), __fsub_rn(gy2, gy1));
    float mx = 0.f;
    for (int n = tid; n < NN; n += 256) {
        float x1, y1, x2, y2, aA;
        anchor_of(n, x1, y1, x2, y2, aA);
        mx = fmaxf(mx, iou_f(x1, y1, x2, y2, aA, gx1, gy1, gx2, gy2, areaG));
    }
    __shared__ float red[256];
    red[tid] = mx;
    __syncthreads();
    for (int s = 128; s > 0; s >>= 1) {
        if (tid < s) red[tid] = fmaxf(red[tid], red[tid + s]);
        __syncthreads();
    }
    if (tid == 0) g_maxpg[blockIdx.x] = red[0];
}

/* ============ kernel 4: assign + losses + proposals ===================== */
__global__ void k_loss(const float* __restrict__ gtb, float* __restrict__ out) {
    __shared__ float sg[GG][4], sArea[GG], sMpg[GG];
    __shared__ float redc[256], redr[256];
    int tid = threadIdx.x;
    int b = blockIdx.x / 36;
    int gid = blockIdx.x * 256 + tid;
    int n = gid - b * NN;

    if (tid < 80) sg[tid >> 2][tid & 3] = __fmul_rn(gtb[b * 80 + tid], 0.03125f);
    __syncthreads();
    if (tid < GG) {
        sArea[tid] = __fmul_rn(__fsub_rn(sg[tid][2], sg[tid][0]),
                               __fsub_rn(sg[tid][3], sg[tid][1]));
        sMpg[tid] = g_maxpg[b * GG + tid];
    }
    __syncthreads();

    float x1, y1, x2, y2, aA;
    anchor_of(n, x1, y1, x2, y2, aA);

    float maxi = -1e30f; int gi = 0; bool pos = false;
#pragma unroll
    for (int g = 0; g < GG; g++) {
        float io = iou_f(x1, y1, x2, y2, aA, sg[g][0], sg[g][1], sg[g][2], sg[g][3],
                         sArea[g]);
        if (io > 0.7f) pos = true;
        if (io == sMpg[g] && sMpg[g] > EPSF) pos = true;
        if (io > maxi) { maxi = io; gi = g; }
    }
    bool neg = (maxi < 0.3f) && !pos;
    float posf = pos ? 1.f : 0.f;

    float gx1 = sg[gi][0], gy1 = sg[gi][1], gx2 = sg[gi][2], gy2 = sg[gi][3];

    float acx = (x1 + x2) * 0.5f, acy = (y1 + y2) * 0.5f;
    float aw = x2 - x1, ah = y2 - y1;
    float gcx = (gx1 + gx2) * 0.5f, gcy = (gy1 + gy2) * 0.5f;
    float gw = gx2 - gx1, gh = gy2 - gy1;
    float t0 = (gcx - acx) / (aw + EPSF);
    float t1 = (gcy - acy) / (ah + EPSF);
    float t2 = logf((gw + EPSF) / (aw + EPSF));
    float t3 = logf((gh + EPSF) / (ah + EPSF));

    int cell = n / 9; int a = n - cell * 9;
    size_t pb = (size_t)(b * 1024 + cell) * 45;
    float conf = g_po[pb + a];
    float o0 = g_po[pb + 9 + a * 4 + 0];
    float o1 = g_po[pb + 9 + a * 4 + 1];
    float o2 = g_po[pb + 9 + a * 4 + 2];
    float o3 = g_po[pb + 9 + a * 4 + 3];

    float clsv = pos ? softplusf(-conf) : (neg ? softplusf(conf) : 0.f);
    float regv = 0.f;
    if (pos) {
        float d0 = o0 - t0, d1 = o1 - t1, d2 = o2 - t2, d3 = o3 - t3;
        float s0 = fabsf(d0) < 1.f ? 0.5f * d0 * d0 : fabsf(d0) - 0.5f;
        float s1 = fabsf(d1) < 1.f ? 0.5f * d1 * d1 : fabsf(d1) - 0.5f;
        float s2 = fabsf(d2) < 1.f ? 0.5f * d2 * d2 : fabsf(d2) - 0.5f;
        float s3 = fabsf(d3) < 1.f ? 0.5f * d3 * d3 : fabsf(d3) - 0.5f;
        regv = s0 + s1 + s2 + s3;
    }

    float pcx = acx + o0 * aw, pcy = acy + o1 * ah;
    float pw = aw * expf(o2), ph = ah * expf(o3);
    float* pr = out + 1 + (size_t)gid * 4;
    pr[0] = (pcx - pw * 0.5f) * posf;
    pr[1] = (pcy - ph * 0.5f) * posf;
    pr[2] = (pcx + pw * 0.5f) * posf;
    pr[3] = (pcy + ph * 0.5f) * posf;
    out[1 + (size_t)BB * NN * 4 + gid] = posf;

    redc[tid] = clsv; redr[tid] = regv;
    __syncthreads();
    for (int s = 128; s > 0; s >>= 1) {
        if (tid < s) { redc[tid] += redc[tid + s]; redr[tid] += redr[tid + s]; }
        __syncthreads();
    }
    if (tid == 0) { g_clsp[blockIdx.x] = redc[0]; g_regp[blockIdx.x] = redr[0]; }
}

/* ============ kernel 5: finalize scalar loss ============================ */
__global__ void k_fin(float* __restrict__ out) {
    float c = 0.f, r = 0.f;
    for (int i = 0; i < 144; i++) { c += g_clsp[i]; r += g_regp[i]; }
    out[0] = (c + 5.f * r) * 0.25f;
}

/* ============ launch ==================================================== */
extern "C" void kernel_launch(void* const* d_in, const int* in_sizes, int n_in,
                              void* d_out, int out_size) {
    const float* fm  = (const float*)d_in[0];
    const float* gtb = (const float*)d_in[1];
    const float* w1  = (const float*)d_in[3];
    const float* b1  = (const float*)d_in[4];
    const float* cw  = (const float*)d_in[5];
    const float* cb  = (const float*)d_in[6];
    const float* rw  = (const float*)d_in[7];
    const float* rb  = (const float*)d_in[8];
    float* out = (float*)d_out;

    cudaFuncSetAttribute(k_convmma, cudaFuncAttributeMaxDynamicSharedMemorySize,
                         SMEM_BYTES);

    k_fmt<<<dim3(32, 64, 4), dim3(32, 8)>>>(fm);
    k_wpack<<<dim3(64, 16), 256>>>(w1);
    k_convmma<<<dim3(32, 4), 256, SMEM_BYTES>>>(b1);
    k_heads<<<128, 256>>>(cw, cb, rw, rb);
    k_maxpg<<<BB * GG, 256>>>(gtb);
    k_loss<<<144, 256>>>(gtb, out);
    k_fin<<<1, 1>>>(out);
}

// round 13
// speedup vs baseline: 3.8128x; 1.8413x over previous
#include <cuda_runtime.h>
#include <cuda_fp16.h>
#include <cstdint>

typedef unsigned int u32;

#define BB 4
#define HID 512
#define GG 20
#define NN (32*32*9)
#define MM (4*32*32)
#define KK (2048*9)
#define KTILES 576              /* 9 taps x 64 channel-chunks of 32 */
#define A_BYTES 10240           /* 128 rows * 80B (32 halves + 8 pad) */
#define B_BYTES 8192            /* 128 n * 32 k * 2B, fragment-packed */
#define STAGE_BYTES (A_BYTES + B_BYTES)   /* 18432 */
#define SMEM_BYTES (3*STAGE_BYTES)        /* 55296 */
#define NFMT (MM*2048)          /* halves: 8388608  */
#define NWF (512*18432)         /* halves: 9437184  */
#define EPSF 1e-8f

/* ---------------- scratch (static device globals; no allocation) ------- */
__device__ uint4 g_fmt4[NFMT/8];              /* pixel-major fp16 input [pix][c] */
__device__ uint4 g_wf4[NWF/8];                /* fragment-packed fp16 weights    */
__device__ float g_hid[MM * HID];             /* relu(conv1) pixel-major         */
__device__ float g_po[MM * 45];               /* per pixel: 9 conf + 36 reg      */
__device__ float g_maxpg[BB * GG];
__device__ float g_clsp[144];
__device__ float g_regp[144];

/* ---------------- helpers ---------------------------------------------- */
__device__ __forceinline__ u32 s2u(const void* p) {
    u32 a;
    asm("{ .reg .u64 t; cvta.to.shared.u64 t, %1; cvt.u32.u64 %0, t; }" : "=r"(a) : "l"(p));
    return a;
}
__device__ __forceinline__ void cpa16(u32 dst, const void* src) {
    asm volatile("cp.async.cg.shared.global [%0], [%1], 16;" :: "r"(dst), "l"(src));
}
__device__ __forceinline__ void cpa16z(u32 dst, const void* src, int srcsize) {
    asm volatile("cp.async.cg.shared.global [%0], [%1], 16, %2;"
                 :: "r"(dst), "l"(src), "r"(srcsize));
}
#define CP_COMMIT() asm volatile("cp.async.commit_group;" ::: "memory")
#define CP_WAIT1()  asm volatile("cp.async.wait_group 1;" ::: "memory")

__device__ __forceinline__ void ldsm4(u32& r0, u32& r1, u32& r2, u32& r3, u32 addr) {
    asm volatile("ldmatrix.sync.aligned.m8n8.x4.shared.b16 {%0,%1,%2,%3}, [%4];"
                 : "=r"(r0), "=r"(r1), "=r"(r2), "=r"(r3) : "r"(addr));
}
__device__ __forceinline__ void mma_f16(float& d0, float& d1, float& d2, float& d3,
                                        u32 a0, u32 a1, u32 a2, u32 a3,
                                        u32 b0, u32 b1) {
    asm volatile(
        "mma.sync.aligned.m16n8k16.row.col.f32.f16.f16.f32 "
        "{%0,%1,%2,%3}, {%4,%5,%6,%7}, {%8,%9}, {%0,%1,%2,%3};"
        : "+f"(d0), "+f"(d1), "+f"(d2), "+f"(d3)
        : "r"(a0), "r"(a1), "r"(a2), "r"(a3), "r"(b0), "r"(b1));
}
__device__ __forceinline__ float softplusf(float z) {
    return fmaxf(z, 0.f) + log1pf(expf(-fabsf(z)));
}
__device__ __forceinline__ void anchor_of(int n, float& x1, float& y1, float& x2,
                                          float& y2, float& areaA) {
    int cell = n / 9;  int a = n - cell * 9;
    int yI = cell >> 5, xI = cell & 31;
    int s = a / 3;     int r = a - s * 3;
    float aw = (float)(2 * (s + 1));
    float ah = __fmul_rn(aw, 0.5f + 0.5f * (float)r);
    float xc = (float)xI + 0.5f, yc = (float)yI + 0.5f;
    float hx = __fmul_rn(0.5f, aw), hy = __fmul_rn(0.5f, ah);
    x1 = fminf(fmaxf(__fsub_rn(xc, hx), 0.f), 32.f);
    y1 = fminf(fmaxf(__fsub_rn(yc, hy), 0.f), 32.f);
    x2 = fminf(fmaxf(__fadd_rn(xc, hx), 0.f), 32.f);
    y2 = fminf(fmaxf(__fadd_rn(yc, hy), 0.f), 32.f);
    areaA = __fmul_rn(__fsub_rn(x2, x1), __fsub_rn(y2, y1));
}
__device__ __forceinline__ float iou_f(float ax1, float ay1, float ax2, float ay2,
                                       float areaA, float gx1, float gy1, float gx2,
                                       float gy2, float areaG) {
    float lx = fmaxf(ax1, gx1), ly = fmaxf(ay1, gy1);
    float rx = fminf(ax2, gx2), ry = fminf(ay2, gy2);
    float iw = fmaxf(__fsub_rn(rx, lx), 0.f);
    float ih = fmaxf(__fsub_rn(ry, ly), 0.f);
    float inter = __fmul_rn(iw, ih);
    float den = __fadd_rn(__fsub_rn(__fadd_rn(areaA, areaG), inter), EPSF);
    return __fdiv_rn(inter, den);
}

/* ============ kernel 0a: transpose fm to pixel-major fp16 =============== */
/* grid (32 pixblk, 64 cblk, 4 b), block (32,8) */
__global__ __launch_bounds__(256) void k_fmt(const float* __restrict__ fm) {
    __shared__ float t[32][33];
    int pb = blockIdx.x * 32, cb = blockIdx.y * 32, b = blockIdx.z;
    int tx = threadIdx.x, ty = threadIdx.y;
    __half* gf = (__half*)g_fmt4;
#pragma unroll
    for (int i = ty; i < 32; i += 8)
        t[i][tx] = __ldg(fm + ((size_t)(b * 2048 + cb + i) << 10) + pb + tx);
    __syncthreads();
#pragma unroll
    for (int i = ty; i < 32; i += 8)
        gf[(((size_t)(b * 1024 + pb + i)) << 11) + cb + tx] = __float2half(t[tx][i]);
}

/* ============ kernel 0b: repack weights into fp16 mma-fragment order ==== */
/* grid (64 cb, 16 nb), 256 thr. Stage layout (halves within 4096-stage):  */
/*   off = wn*1024 + ks*512 + chunk*256 + lane*8 + h8                      */
/*   j = chunk*2 + (h8>>2); r=(h8>>1)&1; hh=h8&1; g=lane>>2; tig=lane&3    */
/*   n = nt*128 + wn*32 + j*8 + g;  klocal = ks*16 + r*8 + 2*tig + hh      */
__global__ __launch_bounds__(256) void k_wpack(const float* __restrict__ w1) {
    __shared__ float s[32][289];
    int cb = blockIdx.x;
    int nb = blockIdx.y;
    int n0b = nb * 32;
    int nt = nb >> 2, wn = nb & 3;
    int tid = threadIdx.x;
    __half* gw = (__half*)g_wf4;
    for (int idx = tid; idx < 32 * 288; idx += 256) {
        int r = idx / 288, cc = idx - r * 288;
        s[r][cc] = __ldg(w1 + (size_t)(n0b + r) * KK + cb * 288 + cc);
    }
    __syncthreads();
    for (int t = 0; t < 9; t++) {
        size_t base = ((size_t)(nt * 576 + t * 64 + cb)) * 4096 + wn * 1024;
#pragma unroll
        for (int q = 0; q < 4; q++) {
            int o = q * 256 + tid;            /* 0..1023 */
            int h8 = o & 7, lane = (o >> 3) & 31;
            int chunk = (o >> 8) & 1, ks = o >> 9;
            int j = chunk * 2 + (h8 >> 2);
            int r = (h8 >> 1) & 1, hh = h8 & 1;
            int g = lane >> 2, tig = lane & 3;
            int nloc = j * 8 + g;
            int klocal = ks * 16 + r * 8 + 2 * tig + hh;
            gw[base + o] = __float2half(s[nloc][klocal * 9 + t]);
        }
    }
}

/* ============ kernel 1: conv1, fp16 HMMA + ldmatrix, cp.async pipeline == */
/* M=4096 N=512; K = 9 taps x 64 chunks of 32 ch. grid (32,4), 256 thr.    */
__global__ __launch_bounds__(256, 1) void k_convmma(const float* __restrict__ b1) {
    extern __shared__ float sm[];
    const u32 sm0 = s2u(sm);
    const int tid = threadIdx.x;
    const int lane = tid & 31, wid = tid >> 5;
    const int g = lane >> 2, tig = lane & 3;
    const int wm = wid >> 2, wn = wid & 3;        /* warp grid 2x4, tile 64x32 */
    const int m0 = blockIdx.x * 128;
    const int nt = blockIdx.y;

    /* producer role: thread pair per pixel row */
    const int pp = tid >> 1, hseg = tid & 1;
    const int mp = m0 + pp;
    const int bbp = mp >> 10, yp = (mp >> 5) & 31, xp = mp & 31;

    /* consumer ldmatrix address offset (within A region of a stage) */
    const u32 aoff = (u32)((wm * 64 + (lane & 7) + ((lane >> 3) & 1) * 8) * 80
                           + ((lane >> 4) & 1) * 16);

    float acc[4][4][4];
#pragma unroll
    for (int i = 0; i < 4; i++)
#pragma unroll
        for (int j = 0; j < 4; j++)
#pragma unroll
            for (int c = 0; c < 4; c++) acc[i][j][c] = 0.f;

#define ISSUE(it, s) do {                                                      \
        int tap = (it) >> 6;                                                   \
        int c0 = ((it) & 63) << 5;                                             \
        u32 aB = sm0 + (u32)((s) * STAGE_BYTES);                               \
        {   /* B: contiguous fragment-packed 8192B per stage */                \
            const uint4* srcB = g_wf4 + (size_t)(nt * 576 + (it)) * 512        \
                                + tid * 2;                                     \
            u32 dB = aB + A_BYTES + (u32)tid * 32;                             \
            cpa16(dB, srcB); cpa16(dB + 16, srcB + 1);                         \
        }                                                                      \
        {   /* A: 16 halves of shifted pixel, zero-fill off-edge */            \
            int dy = tap / 3 - 1, dx = tap - (tap / 3) * 3 - 1;                \
            int yy = yp + dy, xx = xp + dx;                                    \
            int vs = ((unsigned)yy < 32u && (unsigned)xx < 32u) ? 16 : 0;      \
            const uint4* srcA = vs ? g_fmt4 +                                  \
                ((size_t)((bbp << 10) + (yy << 5) + xx)) * 256                 \
                + (c0 >> 3) + hseg * 2 : g_fmt4;                               \
            u32 dA = aB + (u32)(pp * 80 + hseg * 32);                          \
            cpa16z(dA, srcA, vs); cpa16z(dA + 16, srcA + 1, vs);               \
        }                                                                      \
    } while (0)

    ISSUE(0, 0); CP_COMMIT();
    ISSUE(1, 1); CP_COMMIT();

    for (int it = 0; it < KTILES; it++) {
        CP_WAIT1();
        __syncthreads();
        const int s = it % 3;
        if (it + 2 < KTILES) ISSUE(it + 2, (it + 2) % 3);
        CP_COMMIT();

        const char* stg = (const char*)sm + s * STAGE_BYTES;
        const uint4* Bp = (const uint4*)(stg + A_BYTES + wn * 2048 + lane * 16);
        const u32 aS = sm0 + (u32)(s * STAGE_BYTES) + aoff;
#pragma unroll
        for (int ks = 0; ks < 2; ks++) {
            uint4 bc0 = Bp[ks * 64];          /* j0,j1 frags */
            uint4 bc1 = Bp[ks * 64 + 32];     /* j2,j3 frags */
#pragma unroll
            for (int i = 0; i < 4; i++) {
                u32 a0, a1, a2, a3;
                ldsm4(a0, a1, a2, a3, aS + i * 1280 + ks * 32);
                mma_f16(acc[i][0][0], acc[i][0][1], acc[i][0][2], acc[i][0][3],
                        a0, a1, a2, a3, bc0.x, bc0.y);
                mma_f16(acc[i][1][0], acc[i][1][1], acc[i][1][2], acc[i][1][3],
                        a0, a1, a2, a3, bc0.z, bc0.w);
                mma_f16(acc[i][2][0], acc[i][2][1], acc[i][2][2], acc[i][2][3],
                        a0, a1, a2, a3, bc1.x, bc1.y);
                mma_f16(acc[i][3][0], acc[i][3][1], acc[i][3][2], acc[i][3][3],
                        a0, a1, a2, a3, bc1.z, bc1.w);
            }
        }
    }
#undef ISSUE

    /* ---- epilogue: bias + relu -> g_hid ---- */
#pragma unroll
    for (int j = 0; j < 4; j++) {
        int nb = nt * 128 + wn * 32 + j * 8 + 2 * tig;
        float bb0 = b1[nb], bb1 = b1[nb + 1];
#pragma unroll
        for (int i = 0; i < 4; i++) {
            int ma = m0 + wm * 64 + i * 16 + g;
            float2* d0 = (float2*)(g_hid + (size_t)ma * 512 + nb);
            float2* d1 = (float2*)(g_hid + (size_t)(ma + 8) * 512 + nb);
            *d0 = make_float2(fmaxf(acc[i][j][0] + bb0, 0.f),
                              fmaxf(acc[i][j][1] + bb1, 0.f));
            *d1 = make_float2(fmaxf(acc[i][j][2] + bb0, 0.f),
                              fmaxf(acc[i][j][3] + bb1, 0.f));
        }
    }
}

/* ============ kernel 2: 1x1 heads, one thread per (pixel, output) ======= */
__global__ __launch_bounds__(256) void k_heads(const float* __restrict__ cw,
                                               const float* __restrict__ cb,
                                               const float* __restrict__ rw,
                                               const float* __restrict__ rb) {
    int id = blockIdx.x * 256 + threadIdx.x;
    if (id >= MM * 45) return;
    int p = id / 45, n = id - p * 45;
    const float4* a = (const float4*)(g_hid + (size_t)p * 512);
    const float* wrow = (n < 9) ? cw + n * 512 : rw + (n - 9) * 512;
    const float4* w = (const float4*)wrow;
    float4 acc = make_float4(0.f, 0.f, 0.f, 0.f);
#pragma unroll 8
    for (int i = 0; i < 128; i++) {
        float4 av = a[i], wv = __ldg(w + i);
        acc.x += av.x * wv.x; acc.y += av.y * wv.y;
        acc.z += av.z * wv.z; acc.w += av.w * wv.w;
    }
    float bias = (n < 9) ? cb[n] : rb[n - 9];
    g_po[(size_t)p * 45 + n] = (acc.x + acc.y) + (acc.z + acc.w) + bias;
}

/* ============ kernel 3: max IoU per (b,g) =============================== */
__global__ void k_maxpg(const float* __restrict__ gtb) {
    int b = blockIdx.x / GG, g = blockIdx.x % GG;
    int tid = threadIdx.x;
    float gx1 = __fmul_rn(gtb[(b * GG + g) * 4 + 0], 0.03125f);
    float gy1 = __fmul_rn(gtb[(b * GG + g) * 4 + 1], 0.03125f);
    float gx2 = __fmul_rn(gtb[(b * GG + g) * 4 + 2], 0.03125f);
    float gy2 = __fmul_rn(gtb[(b * GG + g) * 4 + 3], 0.03125f);
    float areaG = __fmul_rn(__fsub_rn(gx2, gx1), __fsub_rn(gy2, gy1));
    float mx = 0.f;
    for (int n = tid; n < NN; n += 256) {
        float x1, y1, x2, y2, aA;
        anchor_of(n, x1, y1, x2, y2, aA);
        mx = fmaxf(mx, iou_f(x1, y1, x2, y2, aA, gx1, gy1, gx2, gy2, areaG));
    }
    __shared__ float red[256];
    red[tid] = mx;
    __syncthreads();
    for (int s = 128; s > 0; s >>= 1) {
        if (tid < s) red[tid] = fmaxf(red[tid], red[tid + s]);
        __syncthreads();
    }
    if (tid == 0) g_maxpg[blockIdx.x] = red[0];
}

/* ============ kernel 4: assign + losses + proposals ===================== */
__global__ void k_loss(const float* __restrict__ gtb, float* __restrict__ out) {
    __shared__ float sg[GG][4], sArea[GG], sMpg[GG];
    __shared__ float redc[256], redr[256];
    int tid = threadIdx.x;
    int b = blockIdx.x / 36;
    int gid = blockIdx.x * 256 + tid;
    int n = gid - b * NN;

    if (tid < 80) sg[tid >> 2][tid & 3] = __fmul_rn(gtb[b * 80 + tid], 0.03125f);
    __syncthreads();
    if (tid < GG) {
        sArea[tid] = __fmul_rn(__fsub_rn(sg[tid][2], sg[tid][0]),
                               __fsub_rn(sg[tid][3], sg[tid][1]));
        sMpg[tid] = g_maxpg[b * GG + tid];
    }
    __syncthreads();

    float x1, y1, x2, y2, aA;
    anchor_of(n, x1, y1, x2, y2, aA);

    float maxi = -1e30f; int gi = 0; bool pos = false;
#pragma unroll
    for (int g = 0; g < GG; g++) {
        float io = iou_f(x1, y1, x2, y2, aA, sg[g][0], sg[g][1], sg[g][2], sg[g][3],
                         sArea[g]);
        if (io > 0.7f) pos = true;
        if (io == sMpg[g] && sMpg[g] > EPSF) pos = true;
        if (io > maxi) { maxi = io; gi = g; }
    }
    bool neg = (maxi < 0.3f) && !pos;
    float posf = pos ? 1.f : 0.f;

    float gx1 = sg[gi][0], gy1 = sg[gi][1], gx2 = sg[gi][2], gy2 = sg[gi][3];

    float acx = (x1 + x2) * 0.5f, acy = (y1 + y2) * 0.5f;
    float aw = x2 - x1, ah = y2 - y1;
    float gcx = (gx1 + gx2) * 0.5f, gcy = (gy1 + gy2) * 0.5f;
    float gw = gx2 - gx1, gh = gy2 - gy1;
    float t0 = (gcx - acx) / (aw + EPSF);
    float t1 = (gcy - acy) / (ah + EPSF);
    float t2 = logf((gw + EPSF) / (aw + EPSF));
    float t3 = logf((gh + EPSF) / (ah + EPSF));

    int cell = n / 9; int a = n - cell * 9;
    size_t pb = (size_t)(b * 1024 + cell) * 45;
    float conf = g_po[pb + a];
    float o0 = g_po[pb + 9 + a * 4 + 0];
    float o1 = g_po[pb + 9 + a * 4 + 1];
    float o2 = g_po[pb + 9 + a * 4 + 2];
    float o3 = g_po[pb + 9 + a * 4 + 3];

    float clsv = pos ? softplusf(-conf) : (neg ? softplusf(conf) : 0.f);
    float regv = 0.f;
    if (pos) {
        float d0 = o0 - t0, d1 = o1 - t1, d2 = o2 - t2, d3 = o3 - t3;
        float s0 = fabsf(d0) < 1.f ? 0.5f * d0 * d0 : fabsf(d0) - 0.5f;
        float s1 = fabsf(d1) < 1.f ? 0.5f * d1 * d1 : fabsf(d1) - 0.5f;
        float s2 = fabsf(d2) < 1.f ? 0.5f * d2 * d2 : fabsf(d2) - 0.5f;
        float s3 = fabsf(d3) < 1.f ? 0.5f * d3 * d3 : fabsf(d3) - 0.5f;
        regv = s0 + s1 + s2 + s3;
    }

    float pcx = acx + o0 * aw, pcy = acy + o1 * ah;
    float pw = aw * expf(o2), ph = ah * expf(o3);
    float* pr = out + 1 + (size_t)gid * 4;
    pr[0] = (pcx - pw * 0.5f) * posf;
    pr[1] = (pcy - ph * 0.5f) * posf;
    pr[2] = (pcx + pw * 0.5f) * posf;
    pr[3] = (pcy + ph * 0.5f) * posf;
    out[1 + (size_t)BB * NN * 4 + gid] = posf;

    redc[tid] = clsv; redr[tid] = regv;
    __syncthreads();
    for (int s = 128; s > 0; s >>= 1) {
        if (tid < s) { redc[tid] += redc[tid + s]; redr[tid] += redr[tid + s]; }
        __syncthreads();
    }
    if (tid == 0) { g_clsp[blockIdx.x] = redc[0]; g_regp[blockIdx.x] = redr[0]; }
}

/* ============ kernel 5: finalize scalar loss ============================ */
__global__ void k_fin(float* __restrict__ out) {
    float c = 0.f, r = 0.f;
    for (int i = 0; i < 144; i++) { c += g_clsp[i]; r += g_regp[i]; }
    out[0] = (c + 5.f * r) * 0.25f;
}

/* ============ launch ==================================================== */
extern "C" void kernel_launch(void* const* d_in, const int* in_sizes, int n_in,
                              void* d_out, int out_size) {
    const float* fm  = (const float*)d_in[0];
    const float* gtb = (const float*)d_in[1];
    const float* w1  = (const float*)d_in[3];
    const float* b1  = (const float*)d_in[4];
    const float* cw  = (const float*)d_in[5];
    const float* cb  = (const float*)d_in[6];
    const float* rw  = (const float*)d_in[7];
    const float* rb  = (const float*)d_in[8];
    float* out = (float*)d_out;

    cudaFuncSetAttribute(k_convmma, cudaFuncAttributeMaxDynamicSharedMemorySize,
                         SMEM_BYTES);

    k_fmt<<<dim3(32, 64, 4), dim3(32, 8)>>>(fm);
    k_wpack<<<dim3(64, 16), 256>>>(w1);
    k_convmma<<<dim3(32, 4), 256, SMEM_BYTES>>>(b1);
    k_heads<<<(MM * 45 + 255) / 256, 256>>>(cw, cb, rw, rb);
    k_maxpg<<<BB * GG, 256>>>(gtb);
    k_loss<<<144, 256>>>(gtb, out);
    k_fin<<<1, 1>>>(out);
}